// round 12
// baseline (speedup 1.0000x reference)
#include <cuda_runtime.h>
#include <cuda_bf16.h>
#include <mma.h>
#include <cstdint>

using namespace nvcuda;

#define Bb 256
#define Dd 256
#define Tt 512
#define Hh 512
#define G4 2048
#define Mm (Tt*Bb)   // 131072

// ---------------- device scratch (no runtime allocation allowed) ----------------
__device__ __nv_bfloat16 g_xb[(size_t)Mm*Dd];        // xs as bf16, [t*B+b][d]
__device__ __nv_bfloat16 g_xgb[(size_t)Mm*G4];       // x_gates bf16 (includes biases)
__device__ __nv_bfloat16 g_wih[(size_t)Dd*G4];       // W_ih^T bf16 [k][n]
__device__ __nv_bfloat16 g_whh[(size_t)Hh*G4];       // W_hh^T bf16 [k][n]
__device__ float         g_biasmat[16*G4];           // 16 identical rows of (b_ih+b_hh)
__device__ __nv_bfloat16 g_h[2][(size_t)Bb*Hh];      // double-buffered hidden state
__device__ float         g_plog[64*(size_t)Tt*Bb];   // partial logits per (ut,octet)
__device__ unsigned int  g_ctr[8][32];               // per batch-group counter (128B apart)

__device__ __forceinline__ float tanh_fast(float x) {
    float y; asm("tanh.approx.f32 %0, %1;" : "=f"(y) : "f"(x)); return y;
}
__device__ __forceinline__ float sigm(float x) { return 1.0f / (1.0f + __expf(-x)); }

__device__ __forceinline__ void cp16(void* dst, const void* src) {
    unsigned d = (unsigned)__cvta_generic_to_shared(dst);
    asm volatile("cp.async.cg.shared.global [%0], [%1], 16;" :: "r"(d), "l"(src));
}

__device__ __forceinline__ void ldsm_x4(uint32_t& r0, uint32_t& r1, uint32_t& r2, uint32_t& r3, uint32_t a) {
    asm volatile("ldmatrix.sync.aligned.m8n8.x4.shared.b16 {%0,%1,%2,%3}, [%4];"
                 : "=r"(r0), "=r"(r1), "=r"(r2), "=r"(r3) : "r"(a));
}
__device__ __forceinline__ void ldsm_x4t(uint32_t& r0, uint32_t& r1, uint32_t& r2, uint32_t& r3, uint32_t a) {
    asm volatile("ldmatrix.sync.aligned.m8n8.x4.trans.shared.b16 {%0,%1,%2,%3}, [%4];"
                 : "=r"(r0), "=r"(r1), "=r"(r2), "=r"(r3) : "r"(a));
}
__device__ __forceinline__ void mma16816(float* c, uint32_t a0, uint32_t a1, uint32_t a2, uint32_t a3,
                                         uint32_t b0, uint32_t b1) {
    asm volatile("mma.sync.aligned.m16n8k16.row.col.f32.bf16.bf16.f32 "
                 "{%0,%1,%2,%3},{%4,%5,%6,%7},{%8,%9},{%0,%1,%2,%3};"
                 : "+f"(c[0]), "+f"(c[1]), "+f"(c[2]), "+f"(c[3])
                 : "r"(a0), "r"(a1), "r"(a2), "r"(a3), "r"(b0), "r"(b1));
}

// ---------------- init: zero h0 and counters ----------------
__global__ void k_init() {
    int i = blockIdx.x * blockDim.x + threadIdx.x;
    if (i < 8 * 32) ((unsigned*)g_ctr)[i] = 0u;
    if (i < Bb * Hh) g_h[0][i] = __float2bfloat16(0.0f);
}

// ---------------- weight converts (transpose to [k][n], bf16) ----------------
__global__ void k_convert(const float* __restrict__ Wih, const float* __restrict__ Whh,
                          const float* __restrict__ bih, const float* __restrict__ bhh) {
    int i = blockIdx.x * blockDim.x + threadIdx.x;
    if (i < Dd * G4) {
        int k = i / G4, n = i % G4;
        g_wih[i] = __float2bfloat16(Wih[(size_t)n * Dd + k]);
    }
    if (i < Hh * G4) {
        int k = i / G4, n = i % G4;
        g_whh[i] = __float2bfloat16(Whh[(size_t)n * Hh + k]);
    }
    if (i < 16 * G4) {
        int n = i % G4;
        g_biasmat[i] = bih[n] + bhh[n];
    }
}

// ---------------- transpose x (B,D,T) -> g_xb[(t*B+b)*D + d] bf16 ----------------
__global__ void k_transpose(const float* __restrict__ x) {
    __shared__ float tile[32][33];
    int b  = blockIdx.z;
    int d0 = blockIdx.y * 32, t0 = blockIdx.x * 32;
    int tx = threadIdx.x, ty = threadIdx.y;   // 32 x 8
    const float* src = x + ((size_t)b * Dd + d0) * Tt + t0;
    for (int r = ty; r < 32; r += 8)
        tile[r][tx] = src[(size_t)r * Tt + tx];
    __syncthreads();
    for (int r = ty; r < 32; r += 8)
        g_xb[((size_t)(t0 + r) * Bb + b) * Dd + d0 + tx] = __float2bfloat16(tile[tx][r]);
}

// ---------------- GEMM1: 128x128 tile, 2-stage cp.async; bf16 output via SMEM staging ----
#define GA_LD 72
#define GB_LD 136
#define G1_SMEM (2*128*GA_LD*2 + 2*64*GB_LD*2)   // 71680 B; also reused as 128x132 f32 stage

__global__ void __launch_bounds__(256, 2) k_gemm1() {
    extern __shared__ char smg[];
    __nv_bfloat16 (*As)[128][GA_LD] = (__nv_bfloat16(*)[128][GA_LD])smg;
    __nv_bfloat16 (*Bs)[64][GB_LD]  = (__nv_bfloat16(*)[64][GB_LD])(smg + 2*128*GA_LD*2);

    int n0 = blockIdx.x * 128, m0 = blockIdx.y * 128;   // n fastest -> A-tile reuse in L2
    int tid = threadIdx.x;
    int w = tid >> 5;
    int mw = (w >> 1) * 32, nw = (w & 1) * 64;

    auto load_stage = [&](int c, int s) {
        int k0 = c * 64;
        #pragma unroll
        for (int p = 0; p < 4; p++) {
            int idx = tid + p * 256;
            int r = idx >> 3, cc = (idx & 7) * 8;
            cp16(&As[s][r][cc], &g_xb[(size_t)(m0 + r) * Dd + k0 + cc]);
        }
        #pragma unroll
        for (int p = 0; p < 4; p++) {
            int idx = tid + p * 256;
            int r = idx >> 4, cc = (idx & 15) * 8;
            cp16(&Bs[s][r][cc], &g_wih[(size_t)(k0 + r) * G4 + n0 + cc]);
        }
        asm volatile("cp.async.commit_group;" ::: "memory");
    };

    load_stage(0, 0);

    wmma::fragment<wmma::accumulator, 16, 16, 16, float> acc[2][4];
    #pragma unroll
    for (int i = 0; i < 2; i++)
        #pragma unroll
        for (int j = 0; j < 4; j++)
            wmma::load_matrix_sync(acc[i][j], &g_biasmat[n0 + nw + 16 * j], G4, wmma::mem_row_major);

    #pragma unroll
    for (int c = 0; c < 4; c++) {
        if (c < 3) load_stage(c + 1, (c + 1) & 1);
        if (c < 3) asm volatile("cp.async.wait_group 1;" ::: "memory");
        else       asm volatile("cp.async.wait_group 0;" ::: "memory");
        __syncthreads();
        int s = c & 1;
        #pragma unroll
        for (int kk = 0; kk < 64; kk += 16) {
            wmma::fragment<wmma::matrix_a, 16, 16, 16, __nv_bfloat16, wmma::row_major> af[2];
            wmma::fragment<wmma::matrix_b, 16, 16, 16, __nv_bfloat16, wmma::row_major> bf[4];
            #pragma unroll
            for (int i = 0; i < 2; i++)
                wmma::load_matrix_sync(af[i], &As[s][mw + 16 * i][kk], GA_LD);
            #pragma unroll
            for (int j = 0; j < 4; j++)
                wmma::load_matrix_sync(bf[j], &Bs[s][kk][nw + 16 * j], GB_LD);
            #pragma unroll
            for (int i = 0; i < 2; i++)
                #pragma unroll
                for (int j = 0; j < 4; j++)
                    wmma::mma_sync(acc[i][j], af[i], bf[j], acc[i][j]);
        }
        __syncthreads();
    }

    // epilogue: stage f32 in SMEM, convert to bf16, coalesced global write
    float* Fst = (float*)smg;   // [128][132]
    #pragma unroll
    for (int i = 0; i < 2; i++)
        #pragma unroll
        for (int j = 0; j < 4; j++)
            wmma::store_matrix_sync(&Fst[(size_t)(mw + 16 * i) * 132 + nw + 16 * j],
                                    acc[i][j], 132, wmma::mem_row_major);
    __syncthreads();
    {
        int r = tid >> 1, half = tid & 1;
        const float* src = &Fst[(size_t)r * 132 + half * 64];
        __nv_bfloat16* dst = &g_xgb[(size_t)(m0 + r) * G4 + n0 + half * 64];
        #pragma unroll
        for (int c = 0; c < 64; c += 4) {
            float4 v = *(const float4*)(src + c);
            __nv_bfloat162 lo = __floats2bfloat162_rn(v.x, v.y);
            __nv_bfloat162 hi = __floats2bfloat162_rn(v.z, v.w);
            uint2 pk = make_uint2(*(unsigned*)&lo, *(unsigned*)&hi);
            *(uint2*)(dst + c) = pk;
        }
    }
}

// ---------------- persistent LSTM recurrence: k-split warps, minimal SMEM redundancy ----
// 128 CTAs = bt(0..7) x ut(0..15). Warp w: unit-octet uo = w>>1, k-half ks = w&1.
// Each warp: ALL 32 batch rows (2 A-tiles) x 32 gate-cols (4 gates x 8 units) x K/2.
// B-frags read once; ks=1 partials combined into ks=0 via thread-indexed SMEM scratch.
#define BS_LD 136
#define AS_LD 520
#define CMB_OFF (512*BS_LD*2 + 32*AS_LD*2)
#define DSMEM_BYTES (CMB_OFF + 4*32*33*4)

__global__ void __launch_bounds__(256, 1) k_lstm(const float* __restrict__ Wmlp) {
    extern __shared__ char smem[];
    __nv_bfloat16* Bs = (__nv_bfloat16*)smem;                          // [512][BS_LD]
    __nv_bfloat16* As = (__nv_bfloat16*)(smem + 512 * BS_LD * 2);      // [32][AS_LD]
    float*        Cmb = (float*)(smem + CMB_OFF);                      // [4][32][33]

    int tid = threadIdx.x, w = tid >> 5, lane = tid & 31;
    int ut = blockIdx.x & 15, bt = blockIdx.x >> 4;
    int u0 = ut * 32, b0 = bt * 32;
    int uo = w >> 1;              // unit octet 0..3
    int ks = w & 1;               // k half 0..1
    unsigned* ctr = &g_ctr[bt][0];

    // preload W_hh slice into SMEM: Bs[k][g*32+uu] = W_hh[g*512+u0+uu][k]
    for (int idx = tid; idx < 512 * 16; idx += 256) {
        int k = idx >> 4;
        int col = (idx & 15) * 8;
        int g = col >> 5, uu = col & 31;
        *(uint4*)&Bs[k * BS_LD + col] = *(const uint4*)&g_whh[(size_t)k * G4 + g * 512 + u0 + uu];
    }

    // ldmatrix addressing
    int grp = lane >> 3, rin = lane & 7;
    uint32_t As_u = (uint32_t)__cvta_generic_to_shared(As);
    uint32_t Bs_u = (uint32_t)__cvta_generic_to_shared(Bs);
    uint32_t aBase0 = As_u + (uint32_t)((( (grp & 1) * 8 + rin) * AS_LD + (grp >> 1) * 8) * 2);
    uint32_t aBase1 = As_u + (uint32_t)(((16 + (grp & 1) * 8 + rin) * AS_LD + (grp >> 1) * 8) * 2);
    int bRow = (grp & 1) * 8 + rin;
    int gsel = grp >> 1;          // 0/1 within the gate pair
    uint32_t bBase01 = Bs_u + (uint32_t)((bRow * BS_LD + (gsel * 32 + uo * 8)) * 2);
    uint32_t bBase23 = Bs_u + (uint32_t)((bRow * BS_LD + ((2 + gsel) * 32 + uo * 8)) * 2);
    int kbase = ks * 256;

    // cell ownership (ks==0 warps): rows {q, q+8, q+16, q+24}, cols {u_a, u_a+1}
    int q = lane >> 2;
    int rows[4] = {q, q + 8, q + 16, q + 24};   // [bt0 lo, bt0 hi, bt1 lo, bt1 hi]
    int u_a = uo * 8 + (lane & 3) * 2;
    float2 wm = __ldg((const float2*)&Wmlp[u0 + u_a]);

    float c_reg[8];
    #pragma unroll
    for (int e = 0; e < 8; e++) c_reg[e] = 0.0f;

    // xg prefetch for t=0 (ks==0 warps own the cell): [rowIdx][gate] bf16x2
    __nv_bfloat162 xr[4][4];
    if (ks == 0) {
        #pragma unroll
        for (int ri = 0; ri < 4; ri++) {
            const __nv_bfloat16* p = g_xgb + ((size_t)0 * Bb + b0 + rows[ri]) * G4 + u0 + u_a;
            #pragma unroll
            for (int g = 0; g < 4; g++)
                xr[ri][g] = __ldg((const __nv_bfloat162*)(p + g * 512));
        }
    }

    __syncthreads();

    for (int t = 0; t < Tt; t++) {
        int cur = t & 1, nxt = cur ^ 1;

        // load h (32 x 512 bf16) from L2 into As
        const __nv_bfloat16* hsrc = g_h[cur] + (size_t)b0 * Hh;
        #pragma unroll
        for (int it = 0; it < 8; it++) {
            int idx = tid + it * 256;
            int r = idx >> 6, c = (idx & 63) * 8;
            *(uint4*)&As[r * AS_LD + c] = __ldcg((const uint4*)&hsrc[(size_t)r * Hh + c]);
        }
        __syncthreads();

        // MMA over this warp's k-half: acc[bt][gate][4] -> 8 independent chains of 16
        float acc[2][4][4];
        #pragma unroll
        for (int b = 0; b < 2; b++)
            #pragma unroll
            for (int g = 0; g < 4; g++)
                #pragma unroll
                for (int e = 0; e < 4; e++) acc[b][g][e] = 0.f;

        #pragma unroll
        for (int kc = 0; kc < 16; kc++) {
            int koff = kbase + kc * 16;
            uint32_t a0, a1, a2, a3, c0, c1, c2, c3, q0, q1, q2, q3, s0, s1, s2, s3;
            ldsm_x4 (a0, a1, a2, a3, aBase0  + (uint32_t)(koff * 2));
            ldsm_x4 (c0, c1, c2, c3, aBase1  + (uint32_t)(koff * 2));
            ldsm_x4t(q0, q1, q2, q3, bBase01 + (uint32_t)(koff * BS_LD * 2));
            ldsm_x4t(s0, s1, s2, s3, bBase23 + (uint32_t)(koff * BS_LD * 2));
            mma16816(acc[0][0], a0, a1, a2, a3, q0, q1);
            mma16816(acc[0][1], a0, a1, a2, a3, q2, q3);
            mma16816(acc[0][2], a0, a1, a2, a3, s0, s1);
            mma16816(acc[0][3], a0, a1, a2, a3, s2, s3);
            mma16816(acc[1][0], c0, c1, c2, c3, q0, q1);
            mma16816(acc[1][1], c0, c1, c2, c3, q2, q3);
            mma16816(acc[1][2], c0, c1, c2, c3, s0, s1);
            mma16816(acc[1][3], c0, c1, c2, c3, s2, s3);
        }

        // k-half combine: ks=1 dumps, ks=0 adds (identical per-thread layouts)
        if (ks == 1) {
            float* dst = &Cmb[(uo * 32 + lane) * 33];
            #pragma unroll
            for (int b = 0; b < 2; b++)
                #pragma unroll
                for (int g = 0; g < 4; g++)
                    #pragma unroll
                    for (int e = 0; e < 4; e++)
                        dst[(b * 4 + g) * 4 + e] = acc[b][g][e];
        }
        __syncthreads();

        if (ks == 0) {
            const float* srcc = &Cmb[(uo * 32 + lane) * 33];
            #pragma unroll
            for (int b = 0; b < 2; b++)
                #pragma unroll
                for (int g = 0; g < 4; g++)
                    #pragma unroll
                    for (int e = 0; e < 4; e++)
                        acc[b][g][e] += srcc[(b * 4 + g) * 4 + e];

            // cell: rowIdx ri -> (bt=ri>>1, lohi=ri&1); elem e = lohi*2 + col
            float hv[8];
            #pragma unroll
            for (int ri = 0; ri < 4; ri++) {
                int bq = ri >> 1, lh = ri & 1;
                float2 x0 = __bfloat1622float2(xr[ri][0]);
                float2 x1 = __bfloat1622float2(xr[ri][1]);
                float2 x2 = __bfloat1622float2(xr[ri][2]);
                float2 x3 = __bfloat1622float2(xr[ri][3]);
                #pragma unroll
                for (int cl = 0; cl < 2; cl++) {
                    int e = lh * 2 + cl;
                    float ig = sigm(acc[bq][0][e] + (cl ? x0.y : x0.x));
                    float fg = sigm(acc[bq][1][e] + (cl ? x1.y : x1.x));
                    float gg = tanh_fast(acc[bq][2][e] + (cl ? x2.y : x2.x));
                    float og = sigm(acc[bq][3][e] + (cl ? x3.y : x3.x));
                    float cn = fg * c_reg[ri * 2 + cl] + ig * gg;
                    c_reg[ri * 2 + cl] = cn;
                    hv[ri * 2 + cl] = og * tanh_fast(cn);
                }
            }

            // write h (bf16x2 per row) + partial logits
            #pragma unroll
            for (int ri = 0; ri < 4; ri++) {
                __nv_bfloat162 h2 = __floats2bfloat162_rn(hv[ri * 2], hv[ri * 2 + 1]);
                __stcg((unsigned*)&g_h[nxt][(size_t)(b0 + rows[ri]) * Hh + u0 + u_a], *(unsigned*)&h2);
            }
            {
                float s0 = hv[0] * wm.x + hv[1] * wm.y;
                float s1 = hv[2] * wm.x + hv[3] * wm.y;
                float s2 = hv[4] * wm.x + hv[5] * wm.y;
                float s3 = hv[6] * wm.x + hv[7] * wm.y;
                #pragma unroll
                for (int m = 1; m <= 2; m <<= 1) {
                    s0 += __shfl_xor_sync(0xffffffffu, s0, m);
                    s1 += __shfl_xor_sync(0xffffffffu, s1, m);
                    s2 += __shfl_xor_sync(0xffffffffu, s2, m);
                    s3 += __shfl_xor_sync(0xffffffffu, s3, m);
                }
                if ((lane & 3) == 0) {
                    int slot = ut * 4 + uo;
                    float* pb = &g_plog[((size_t)slot * Tt + t) * Bb + b0];
                    pb[rows[0]] = s0;
                    pb[rows[1]] = s1;
                    pb[rows[2]] = s2;
                    pb[rows[3]] = s3;
                }
            }

            // xg prefetch for t+1 (in flight across the barrier wait)
            if (t + 1 < Tt) {
                #pragma unroll
                for (int ri = 0; ri < 4; ri++) {
                    const __nv_bfloat16* p = g_xgb + ((size_t)(t + 1) * Bb + b0 + rows[ri]) * G4 + u0 + u_a;
                    #pragma unroll
                    for (int g = 0; g < 4; g++)
                        xr[ri][g] = __ldg((const __nv_bfloat162*)(p + g * 512));
                }
            }
        }

        // group barrier: 16 CTAs of this batch group (skip after last step)
        if (t + 1 < Tt) {
            __syncthreads();
            if (tid == 0) {
                asm volatile("red.release.gpu.global.add.u32 [%0], 1;" :: "l"(ctr) : "memory");
                unsigned tgt = 16u * (unsigned)(t + 1);
                unsigned v;
                do {
                    asm volatile("ld.acquire.gpu.global.u32 %0, [%1];" : "=r"(v) : "l"(ctr) : "memory");
                } while (v < tgt);
            }
            __syncthreads();
        }
    }
}

// ---------------- reduce partial logits -> sigmoid -> out (B, T) ----------------
__global__ void k_out(const float* __restrict__ bmlp, float* __restrict__ out) {
    int t = blockIdx.x, b = threadIdx.x;
    float s = bmlp[0];
    #pragma unroll
    for (int j = 0; j < 64; j++)
        s += g_plog[((size_t)j * Tt + t) * Bb + b];
    out[(size_t)b * Tt + t] = 1.0f / (1.0f + __expf(-s));
}

// ---------------- launch ----------------
extern "C" void kernel_launch(void* const* d_in, const int* in_sizes, int n_in,
                              void* d_out, int out_size) {
    const float* x    = (const float*)d_in[0];
    const float* Wih  = (const float*)d_in[1];
    const float* Whh  = (const float*)d_in[2];
    const float* bih  = (const float*)d_in[3];
    const float* bhh  = (const float*)d_in[4];
    const float* Wmlp = (const float*)d_in[5];
    const float* bmlp = (const float*)d_in[6];
    float* out = (float*)d_out;

    k_init<<<512, 256>>>();
    k_convert<<<4096, 256>>>(Wih, Whh, bih, bhh);
    k_transpose<<<dim3(Tt / 32, Dd / 32, Bb), dim3(32, 8)>>>(x);

    cudaFuncSetAttribute(k_gemm1, cudaFuncAttributeMaxDynamicSharedMemorySize, G1_SMEM);
    k_gemm1<<<dim3(G4 / 128, Mm / 128), 256, G1_SMEM>>>();   // n fastest

    cudaFuncSetAttribute(k_lstm, cudaFuncAttributeMaxDynamicSharedMemorySize, DSMEM_BYTES);
    k_lstm<<<128, 256, DSMEM_BYTES>>>(Wmlp);

    k_out<<<Tt, Bb>>>(bmlp, out);
}

// round 13
// speedup vs baseline: 1.2250x; 1.2250x over previous
#include <cuda_runtime.h>
#include <cuda_bf16.h>
#include <mma.h>
#include <cstdint>

using namespace nvcuda;

#define Bb 256
#define Dd 256
#define Tt 512
#define Hh 512
#define G4 2048
#define Mm (Tt*Bb)   // 131072

// ---------------- device scratch (no runtime allocation allowed) ----------------
__device__ __nv_bfloat16 g_xb[(size_t)Mm*Dd];        // xs as bf16, [t*B+b][d]
__device__ float         g_xg[(size_t)Mm*G4];        // x_gates fp32 (includes biases)
__device__ __nv_bfloat16 g_wih[(size_t)Dd*G4];       // W_ih^T bf16 [k][n]
__device__ __nv_bfloat16 g_whh[(size_t)Hh*G4];       // W_hh^T bf16 [k][n]
__device__ float         g_biasmat[16*G4];           // 16 identical rows of (b_ih+b_hh)
__device__ __nv_bfloat16 g_h[2][(size_t)Bb*Hh];      // double-buffered hidden state
__device__ float         g_plog[64*(size_t)Tt*Bb];   // partial logits per (ut,octet)
__device__ unsigned int  g_ctr[8][32];               // per batch-group counter (128B apart)

__device__ __forceinline__ float tanh_fast(float x) {
    float y; asm("tanh.approx.f32 %0, %1;" : "=f"(y) : "f"(x)); return y;
}
__device__ __forceinline__ float sigm(float x) { return 1.0f / (1.0f + __expf(-x)); }

__device__ __forceinline__ void cp16(void* dst, const void* src) {
    unsigned d = (unsigned)__cvta_generic_to_shared(dst);
    asm volatile("cp.async.cg.shared.global [%0], [%1], 16;" :: "r"(d), "l"(src));
}

__device__ __forceinline__ void ldsm_x4(uint32_t& r0, uint32_t& r1, uint32_t& r2, uint32_t& r3, uint32_t a) {
    asm volatile("ldmatrix.sync.aligned.m8n8.x4.shared.b16 {%0,%1,%2,%3}, [%4];"
                 : "=r"(r0), "=r"(r1), "=r"(r2), "=r"(r3) : "r"(a));
}
__device__ __forceinline__ void ldsm_x4t(uint32_t& r0, uint32_t& r1, uint32_t& r2, uint32_t& r3, uint32_t a) {
    asm volatile("ldmatrix.sync.aligned.m8n8.x4.trans.shared.b16 {%0,%1,%2,%3}, [%4];"
                 : "=r"(r0), "=r"(r1), "=r"(r2), "=r"(r3) : "r"(a));
}
__device__ __forceinline__ void mma16816(float* c, uint32_t a0, uint32_t a1, uint32_t a2, uint32_t a3,
                                         uint32_t b0, uint32_t b1) {
    asm volatile("mma.sync.aligned.m16n8k16.row.col.f32.bf16.bf16.f32 "
                 "{%0,%1,%2,%3},{%4,%5,%6,%7},{%8,%9},{%0,%1,%2,%3};"
                 : "+f"(c[0]), "+f"(c[1]), "+f"(c[2]), "+f"(c[3])
                 : "r"(a0), "r"(a1), "r"(a2), "r"(a3), "r"(b0), "r"(b1));
}

// ---------------- init: zero h0 and counters ----------------
__global__ void k_init() {
    int i = blockIdx.x * blockDim.x + threadIdx.x;
    if (i < 8 * 32) ((unsigned*)g_ctr)[i] = 0u;
    if (i < Bb * Hh) g_h[0][i] = __float2bfloat16(0.0f);
}

// ---------------- weight converts (transpose to [k][n], bf16) ----------------
__global__ void k_convert(const float* __restrict__ Wih, const float* __restrict__ Whh,
                          const float* __restrict__ bih, const float* __restrict__ bhh) {
    int i = blockIdx.x * blockDim.x + threadIdx.x;
    if (i < Dd * G4) {
        int k = i / G4, n = i % G4;
        g_wih[i] = __float2bfloat16(Wih[(size_t)n * Dd + k]);
    }
    if (i < Hh * G4) {
        int k = i / G4, n = i % G4;
        g_whh[i] = __float2bfloat16(Whh[(size_t)n * Hh + k]);
    }
    if (i < 16 * G4) {
        int n = i % G4;
        g_biasmat[i] = bih[n] + bhh[n];
    }
}

// ---------------- transpose x (B,D,T) -> g_xb[(t*B+b)*D + d] bf16 ----------------
__global__ void k_transpose(const float* __restrict__ x) {
    __shared__ float tile[32][33];
    int b  = blockIdx.z;
    int d0 = blockIdx.y * 32, t0 = blockIdx.x * 32;
    int tx = threadIdx.x, ty = threadIdx.y;   // 32 x 8
    const float* src = x + ((size_t)b * Dd + d0) * Tt + t0;
    for (int r = ty; r < 32; r += 8)
        tile[r][tx] = src[(size_t)r * Tt + tx];
    __syncthreads();
    for (int r = ty; r < 32; r += 8)
        g_xb[((size_t)(t0 + r) * Bb + b) * Dd + d0 + tx] = __float2bfloat16(tile[tx][r]);
}

// ---------------- GEMM1 (R9/R11 version, 670us): 128x128 tile, 2-stage cp.async ----------
#define GA_LD 72
#define GB_LD 136
#define G1_SMEM (2*128*GA_LD*2 + 2*64*GB_LD*2)

__global__ void __launch_bounds__(256, 2) k_gemm1() {
    extern __shared__ char smg[];
    __nv_bfloat16 (*As)[128][GA_LD] = (__nv_bfloat16(*)[128][GA_LD])smg;
    __nv_bfloat16 (*Bs)[64][GB_LD]  = (__nv_bfloat16(*)[64][GB_LD])(smg + 2*128*GA_LD*2);

    int n0 = blockIdx.x * 128, m0 = blockIdx.y * 128;   // n fastest -> A-tile reuse in L2
    int tid = threadIdx.x;
    int w = tid >> 5;
    int mw = (w >> 1) * 32, nw = (w & 1) * 64;

    auto load_stage = [&](int c, int s) {
        int k0 = c * 64;
        #pragma unroll
        for (int p = 0; p < 4; p++) {
            int idx = tid + p * 256;
            int r = idx >> 3, cc = (idx & 7) * 8;
            cp16(&As[s][r][cc], &g_xb[(size_t)(m0 + r) * Dd + k0 + cc]);
        }
        #pragma unroll
        for (int p = 0; p < 4; p++) {
            int idx = tid + p * 256;
            int r = idx >> 4, cc = (idx & 15) * 8;
            cp16(&Bs[s][r][cc], &g_wih[(size_t)(k0 + r) * G4 + n0 + cc]);
        }
        asm volatile("cp.async.commit_group;" ::: "memory");
    };

    load_stage(0, 0);

    wmma::fragment<wmma::accumulator, 16, 16, 16, float> acc[2][4];
    #pragma unroll
    for (int i = 0; i < 2; i++)
        #pragma unroll
        for (int j = 0; j < 4; j++)
            wmma::load_matrix_sync(acc[i][j], &g_biasmat[n0 + nw + 16 * j], G4, wmma::mem_row_major);

    #pragma unroll
    for (int c = 0; c < 4; c++) {
        if (c < 3) load_stage(c + 1, (c + 1) & 1);
        if (c < 3) asm volatile("cp.async.wait_group 1;" ::: "memory");
        else       asm volatile("cp.async.wait_group 0;" ::: "memory");
        __syncthreads();
        int s = c & 1;
        #pragma unroll
        for (int kk = 0; kk < 64; kk += 16) {
            wmma::fragment<wmma::matrix_a, 16, 16, 16, __nv_bfloat16, wmma::row_major> af[2];
            wmma::fragment<wmma::matrix_b, 16, 16, 16, __nv_bfloat16, wmma::row_major> bf[4];
            #pragma unroll
            for (int i = 0; i < 2; i++)
                wmma::load_matrix_sync(af[i], &As[s][mw + 16 * i][kk], GA_LD);
            #pragma unroll
            for (int j = 0; j < 4; j++)
                wmma::load_matrix_sync(bf[j], &Bs[s][kk][nw + 16 * j], GB_LD);
            #pragma unroll
            for (int i = 0; i < 2; i++)
                #pragma unroll
                for (int j = 0; j < 4; j++)
                    wmma::mma_sync(acc[i][j], af[i], bf[j], acc[i][j]);
        }
        __syncthreads();
    }
    #pragma unroll
    for (int i = 0; i < 2; i++)
        #pragma unroll
        for (int j = 0; j < 4; j++)
            wmma::store_matrix_sync(&g_xg[(size_t)(m0 + mw + 16 * i) * G4 + n0 + nw + 16 * j],
                                    acc[i][j], G4, wmma::mem_row_major);
}

// ---------------- persistent LSTM recurrence: 2 CTAs/SM for latency hiding ----------------
// 256 CTAs = bt(0..7) x ut(0..31). CTA: 32 batch x 16 units (64 gate-cols), K=512.
// 128 threads = 4 warps: bh = w&1 (batch half), uo = w>>1 (unit octet 0..1).
// Register-resident cell (R11 structure), column stride 16 per gate.
#define BS_LD 72
#define AS_LD 520
#define DSMEM_BYTES (512*BS_LD*2 + 32*AS_LD*2)   // 73728 + 33280 = 107008

__global__ void __launch_bounds__(128, 2) k_lstm(const float* __restrict__ Wmlp) {
    extern __shared__ char smem[];
    __nv_bfloat16* Bs = (__nv_bfloat16*)smem;                          // [512][BS_LD]
    __nv_bfloat16* As = (__nv_bfloat16*)(smem + 512 * BS_LD * 2);      // [32][AS_LD]

    int tid = threadIdx.x, w = tid >> 5, lane = tid & 31;
    int ut = blockIdx.x & 31, bt = blockIdx.x >> 5;
    int u0 = ut * 16, b0 = bt * 32;
    int bh = (w & 1);             // batch half (16 rows)
    int uo = w >> 1;              // unit octet 0..1
    unsigned* ctr = &g_ctr[bt][0];

    // preload W_hh slice into SMEM: Bs[k][g*16+uu] = W_hh[g*512+u0+uu][k], uu in [0,16)
    for (int idx = tid; idx < 512 * 8; idx += 128) {
        int k = idx >> 3;
        int col = (idx & 7) * 8;
        int g = col >> 4, uu = col & 15;
        *(uint4*)&Bs[k * BS_LD + col] = *(const uint4*)&g_whh[(size_t)k * G4 + g * 512 + u0 + uu];
    }

    // ldmatrix addressing
    int grp = lane >> 3, rin = lane & 7;
    uint32_t As_u = (uint32_t)__cvta_generic_to_shared(As);
    uint32_t Bs_u = (uint32_t)__cvta_generic_to_shared(Bs);
    uint32_t aBase = As_u + (uint32_t)(((bh * 16 + (grp & 1) * 8 + rin) * AS_LD + (grp >> 1) * 8) * 2);
    int bRow = (grp & 1) * 8 + rin;
    int gsel = grp >> 1;          // 0/1
    uint32_t bBase01 = Bs_u + (uint32_t)((bRow * BS_LD + (gsel * 16 + uo * 8)) * 2);
    uint32_t bBase23 = Bs_u + (uint32_t)((bRow * BS_LD + ((2 + gsel) * 16 + uo * 8)) * 2);

    // cell ownership (m16n8 D fragment layout): rows {r_lo, r_lo+8}, cols {u_a, u_a+1}
    int r_lo = bh * 16 + (lane >> 2);
    int r_hi = r_lo + 8;
    int u_a  = uo * 8 + (lane & 3) * 2;
    float2 wm = __ldg((const float2*)&Wmlp[u0 + u_a]);

    float c_reg[4] = {0.f, 0.f, 0.f, 0.f};

    // xg prefetch for t=0: per gate, float2 at (row, col u0+g*512+u_a), both rows
    float2 xlo[4], xhi[4];
    {
        const float* plo = g_xg + ((size_t)0 * Bb + b0 + r_lo) * G4 + u0 + u_a;
        const float* phi = g_xg + ((size_t)0 * Bb + b0 + r_hi) * G4 + u0 + u_a;
        #pragma unroll
        for (int g = 0; g < 4; g++) {
            xlo[g] = __ldg((const float2*)(plo + g * 512));
            xhi[g] = __ldg((const float2*)(phi + g * 512));
        }
    }

    __syncthreads();

    for (int t = 0; t < Tt; t++) {
        int cur = t & 1, nxt = cur ^ 1;

        // load h (32 x 512 bf16) from L2 into As
        const __nv_bfloat16* hsrc = g_h[cur] + (size_t)b0 * Hh;
        #pragma unroll
        for (int it = 0; it < 16; it++) {
            int idx = tid + it * 128;
            int r = idx >> 6, c = (idx & 63) * 8;
            *(uint4*)&As[r * AS_LD + c] = __ldcg((const uint4*)&hsrc[(size_t)r * Hh + c]);
        }
        __syncthreads();

        // MMA: acc[gate][k-parity][4elem] -> 8 independent chains of 16
        float acc[4][2][4];
        #pragma unroll
        for (int g = 0; g < 4; g++)
            #pragma unroll
            for (int p = 0; p < 2; p++)
                #pragma unroll
                for (int e = 0; e < 4; e++) acc[g][p][e] = 0.f;

        #pragma unroll
        for (int kc = 0; kc < 16; kc++) {
            #pragma unroll
            for (int p = 0; p < 2; p++) {
                int koff = kc * 32 + p * 16;
                uint32_t a0, a1, a2, a3, q0, q1, q2, q3, s0, s1, s2, s3;
                ldsm_x4 (a0, a1, a2, a3, aBase   + (uint32_t)(koff * 2));
                ldsm_x4t(q0, q1, q2, q3, bBase01 + (uint32_t)(koff * BS_LD * 2));
                ldsm_x4t(s0, s1, s2, s3, bBase23 + (uint32_t)(koff * BS_LD * 2));
                mma16816(acc[0][p], a0, a1, a2, a3, q0, q1);
                mma16816(acc[1][p], a0, a1, a2, a3, q2, q3);
                mma16816(acc[2][p], a0, a1, a2, a3, s0, s1);
                mma16816(acc[3][p], a0, a1, a2, a3, s2, s3);
            }
        }

        // combine k-parity chains
        float gv0[4], gv1[4], gv2[4], gv3[4];
        #pragma unroll
        for (int e = 0; e < 4; e++) {
            gv0[e] = acc[0][0][e] + acc[0][1][e];
            gv1[e] = acc[1][0][e] + acc[1][1][e];
            gv2[e] = acc[2][0][e] + acc[2][1][e];
            gv3[e] = acc[3][0][e] + acc[3][1][e];
        }

        // cell (registers only): e = {lo/ua, lo/ub, hi/ua, hi/ub}
        float xv0[4] = {xlo[0].x, xlo[0].y, xhi[0].x, xhi[0].y};
        float xv1[4] = {xlo[1].x, xlo[1].y, xhi[1].x, xhi[1].y};
        float xv2[4] = {xlo[2].x, xlo[2].y, xhi[2].x, xhi[2].y};
        float xv3[4] = {xlo[3].x, xlo[3].y, xhi[3].x, xhi[3].y};
        float hv[4];
        #pragma unroll
        for (int e = 0; e < 4; e++) {
            float ig = sigm(gv0[e] + xv0[e]);
            float fg = sigm(gv1[e] + xv1[e]);
            float gg = tanh_fast(gv2[e] + xv2[e]);
            float og = sigm(gv3[e] + xv3[e]);
            float cn = fg * c_reg[e] + ig * gg;
            c_reg[e] = cn;
            hv[e] = og * tanh_fast(cn);
        }

        // write h (bf16x2 per row)
        {
            __nv_bfloat162 lo2 = __floats2bfloat162_rn(hv[0], hv[1]);
            __nv_bfloat162 hi2 = __floats2bfloat162_rn(hv[2], hv[3]);
            __stcg((unsigned*)&g_h[nxt][(size_t)(b0 + r_lo) * Hh + u0 + u_a], *(unsigned*)&lo2);
            __stcg((unsigned*)&g_h[nxt][(size_t)(b0 + r_hi) * Hh + u0 + u_a], *(unsigned*)&hi2);
        }

        // partial logits: reduce over the 4 threads covering this row's octet
        {
            float s_lo = hv[0] * wm.x + hv[1] * wm.y;
            float s_hi = hv[2] * wm.x + hv[3] * wm.y;
            s_lo += __shfl_xor_sync(0xffffffffu, s_lo, 1);
            s_lo += __shfl_xor_sync(0xffffffffu, s_lo, 2);
            s_hi += __shfl_xor_sync(0xffffffffu, s_hi, 1);
            s_hi += __shfl_xor_sync(0xffffffffu, s_hi, 2);
            if ((lane & 3) == 0) {
                int slot = ut * 2 + uo;
                g_plog[((size_t)slot * Tt + t) * Bb + b0 + r_lo] = s_lo;
                g_plog[((size_t)slot * Tt + t) * Bb + b0 + r_hi] = s_hi;
            }
        }

        // xg prefetch for t+1 (in flight across the barrier wait)
        if (t + 1 < Tt) {
            const float* plo = g_xg + ((size_t)(t + 1) * Bb + b0 + r_lo) * G4 + u0 + u_a;
            const float* phi = g_xg + ((size_t)(t + 1) * Bb + b0 + r_hi) * G4 + u0 + u_a;
            #pragma unroll
            for (int g = 0; g < 4; g++) {
                xlo[g] = __ldg((const float2*)(plo + g * 512));
                xhi[g] = __ldg((const float2*)(phi + g * 512));
            }
        }

        // group barrier: 32 CTAs of this batch group (skip after last step)
        if (t + 1 < Tt) {
            __syncthreads();
            if (tid == 0) {
                asm volatile("red.release.gpu.global.add.u32 [%0], 1;" :: "l"(ctr) : "memory");
                unsigned tgt = 32u * (unsigned)(t + 1);
                unsigned v;
                do {
                    asm volatile("ld.acquire.gpu.global.u32 %0, [%1];" : "=r"(v) : "l"(ctr) : "memory");
                } while (v < tgt);
            }
            __syncthreads();
        }
    }
}

// ---------------- reduce partial logits -> sigmoid -> out (B, T) ----------------
__global__ void k_out(const float* __restrict__ bmlp, float* __restrict__ out) {
    int t = blockIdx.x, b = threadIdx.x;
    float s = bmlp[0];
    #pragma unroll
    for (int j = 0; j < 64; j++)
        s += g_plog[((size_t)j * Tt + t) * Bb + b];
    out[(size_t)b * Tt + t] = 1.0f / (1.0f + __expf(-s));
}

// ---------------- launch ----------------
extern "C" void kernel_launch(void* const* d_in, const int* in_sizes, int n_in,
                              void* d_out, int out_size) {
    const float* x    = (const float*)d_in[0];
    const float* Wih  = (const float*)d_in[1];
    const float* Whh  = (const float*)d_in[2];
    const float* bih  = (const float*)d_in[3];
    const float* bhh  = (const float*)d_in[4];
    const float* Wmlp = (const float*)d_in[5];
    const float* bmlp = (const float*)d_in[6];
    float* out = (float*)d_out;

    k_init<<<512, 256>>>();
    k_convert<<<4096, 256>>>(Wih, Whh, bih, bhh);
    k_transpose<<<dim3(Tt / 32, Dd / 32, Bb), dim3(32, 8)>>>(x);

    cudaFuncSetAttribute(k_gemm1, cudaFuncAttributeMaxDynamicSharedMemorySize, G1_SMEM);
    k_gemm1<<<dim3(G4 / 128, Mm / 128), 256, G1_SMEM>>>();   // n fastest

    cudaFuncSetAttribute(k_lstm, cudaFuncAttributeMaxDynamicSharedMemorySize, DSMEM_BYTES);
    k_lstm<<<256, 128, DSMEM_BYTES>>>(Wmlp);

    k_out<<<Tt, Bb>>>(bmlp, out);
}

// round 14
// speedup vs baseline: 1.3463x; 1.0990x over previous
#include <cuda_runtime.h>
#include <cuda_bf16.h>
#include <mma.h>
#include <cstdint>

using namespace nvcuda;

#define Bb 256
#define Dd 256
#define Tt 512
#define Hh 512
#define G4 2048
#define Mm (Tt*Bb)   // 131072

// ---------------- device scratch (no runtime allocation allowed) ----------------
__device__ __nv_bfloat16 g_xb[(size_t)Mm*Dd];        // xs as bf16, [t*B+b][d]
__device__ float         g_xg[(size_t)Mm*G4];        // x_gates fp32 (includes biases)
__device__ __nv_bfloat16 g_wih[(size_t)Dd*G4];       // W_ih^T bf16 [k][n]
__device__ __nv_bfloat16 g_whh[(size_t)Hh*G4];       // W_hh^T bf16 [k][n]
__device__ float         g_biasmat[16*G4];           // 16 identical rows of (b_ih+b_hh)
__device__ __nv_bfloat16 g_h[2][(size_t)Bb*Hh];      // double-buffered hidden state
__device__ float         g_plog[64*(size_t)Tt*Bb];   // partial logits per (ut,octet)
__device__ unsigned int  g_ctr[8][32];               // per batch-group counter (128B apart)

__device__ __forceinline__ float tanh_fast(float x) {
    float y; asm("tanh.approx.f32 %0, %1;" : "=f"(y) : "f"(x)); return y;
}
// sigmoid via tanh: 1 MUFU + 2 FMA (vs 2 MUFU for expf+rcp)
__device__ __forceinline__ float sigm(float x) { return fmaf(tanh_fast(x * 0.5f), 0.5f, 0.5f); }

__device__ __forceinline__ void cp16(void* dst, const void* src) {
    unsigned d = (unsigned)__cvta_generic_to_shared(dst);
    asm volatile("cp.async.cg.shared.global [%0], [%1], 16;" :: "r"(d), "l"(src));
}

__device__ __forceinline__ void ldsm_x4(uint32_t& r0, uint32_t& r1, uint32_t& r2, uint32_t& r3, uint32_t a) {
    asm volatile("ldmatrix.sync.aligned.m8n8.x4.shared.b16 {%0,%1,%2,%3}, [%4];"
                 : "=r"(r0), "=r"(r1), "=r"(r2), "=r"(r3) : "r"(a));
}
__device__ __forceinline__ void ldsm_x4t(uint32_t& r0, uint32_t& r1, uint32_t& r2, uint32_t& r3, uint32_t a) {
    asm volatile("ldmatrix.sync.aligned.m8n8.x4.trans.shared.b16 {%0,%1,%2,%3}, [%4];"
                 : "=r"(r0), "=r"(r1), "=r"(r2), "=r"(r3) : "r"(a));
}
__device__ __forceinline__ void mma16816(float* c, uint32_t a0, uint32_t a1, uint32_t a2, uint32_t a3,
                                         uint32_t b0, uint32_t b1) {
    asm volatile("mma.sync.aligned.m16n8k16.row.col.f32.bf16.bf16.f32 "
                 "{%0,%1,%2,%3},{%4,%5,%6,%7},{%8,%9},{%0,%1,%2,%3};"
                 : "+f"(c[0]), "+f"(c[1]), "+f"(c[2]), "+f"(c[3])
                 : "r"(a0), "r"(a1), "r"(a2), "r"(a3), "r"(b0), "r"(b1));
}

// ---------------- init: zero h0 and counters ----------------
__global__ void k_init() {
    int i = blockIdx.x * blockDim.x + threadIdx.x;
    if (i < 8 * 32) ((unsigned*)g_ctr)[i] = 0u;
    if (i < Bb * Hh) g_h[0][i] = __float2bfloat16(0.0f);
}

// ---------------- weight converts (transpose to [k][n], bf16) ----------------
__global__ void k_convert(const float* __restrict__ Wih, const float* __restrict__ Whh,
                          const float* __restrict__ bih, const float* __restrict__ bhh) {
    int i = blockIdx.x * blockDim.x + threadIdx.x;
    if (i < Dd * G4) {
        int k = i / G4, n = i % G4;
        g_wih[i] = __float2bfloat16(Wih[(size_t)n * Dd + k]);
    }
    if (i < Hh * G4) {
        int k = i / G4, n = i % G4;
        g_whh[i] = __float2bfloat16(Whh[(size_t)n * Hh + k]);
    }
    if (i < 16 * G4) {
        int n = i % G4;
        g_biasmat[i] = bih[n] + bhh[n];
    }
}

// ---------------- transpose x (B,D,T) -> g_xb[(t*B+b)*D + d] bf16 ----------------
__global__ void k_transpose(const float* __restrict__ x) {
    __shared__ float tile[32][33];
    int b  = blockIdx.z;
    int d0 = blockIdx.y * 32, t0 = blockIdx.x * 32;
    int tx = threadIdx.x, ty = threadIdx.y;   // 32 x 8
    const float* src = x + ((size_t)b * Dd + d0) * Tt + t0;
    for (int r = ty; r < 32; r += 8)
        tile[r][tx] = src[(size_t)r * Tt + tx];
    __syncthreads();
    for (int r = ty; r < 32; r += 8)
        g_xb[((size_t)(t0 + r) * Bb + b) * Dd + d0 + tx] = __float2bfloat16(tile[tx][r]);
}

// ---------------- GEMM1 (proven 670us): 128x128 tile, 2-stage cp.async ----------
#define GA_LD 72
#define GB_LD 136
#define G1_SMEM (2*128*GA_LD*2 + 2*64*GB_LD*2)

__global__ void __launch_bounds__(256, 2) k_gemm1() {
    extern __shared__ char smg[];
    __nv_bfloat16 (*As)[128][GA_LD] = (__nv_bfloat16(*)[128][GA_LD])smg;
    __nv_bfloat16 (*Bs)[64][GB_LD]  = (__nv_bfloat16(*)[64][GB_LD])(smg + 2*128*GA_LD*2);

    int n0 = blockIdx.x * 128, m0 = blockIdx.y * 128;   // n fastest -> A-tile reuse in L2
    int tid = threadIdx.x;
    int w = tid >> 5;
    int mw = (w >> 1) * 32, nw = (w & 1) * 64;

    auto load_stage = [&](int c, int s) {
        int k0 = c * 64;
        #pragma unroll
        for (int p = 0; p < 4; p++) {
            int idx = tid + p * 256;
            int r = idx >> 3, cc = (idx & 7) * 8;
            cp16(&As[s][r][cc], &g_xb[(size_t)(m0 + r) * Dd + k0 + cc]);
        }
        #pragma unroll
        for (int p = 0; p < 4; p++) {
            int idx = tid + p * 256;
            int r = idx >> 4, cc = (idx & 15) * 8;
            cp16(&Bs[s][r][cc], &g_wih[(size_t)(k0 + r) * G4 + n0 + cc]);
        }
        asm volatile("cp.async.commit_group;" ::: "memory");
    };

    load_stage(0, 0);

    wmma::fragment<wmma::accumulator, 16, 16, 16, float> acc[2][4];
    #pragma unroll
    for (int i = 0; i < 2; i++)
        #pragma unroll
        for (int j = 0; j < 4; j++)
            wmma::load_matrix_sync(acc[i][j], &g_biasmat[n0 + nw + 16 * j], G4, wmma::mem_row_major);

    #pragma unroll
    for (int c = 0; c < 4; c++) {
        if (c < 3) load_stage(c + 1, (c + 1) & 1);
        if (c < 3) asm volatile("cp.async.wait_group 1;" ::: "memory");
        else       asm volatile("cp.async.wait_group 0;" ::: "memory");
        __syncthreads();
        int s = c & 1;
        #pragma unroll
        for (int kk = 0; kk < 64; kk += 16) {
            wmma::fragment<wmma::matrix_a, 16, 16, 16, __nv_bfloat16, wmma::row_major> af[2];
            wmma::fragment<wmma::matrix_b, 16, 16, 16, __nv_bfloat16, wmma::row_major> bf[4];
            #pragma unroll
            for (int i = 0; i < 2; i++)
                wmma::load_matrix_sync(af[i], &As[s][mw + 16 * i][kk], GA_LD);
            #pragma unroll
            for (int j = 0; j < 4; j++)
                wmma::load_matrix_sync(bf[j], &Bs[s][kk][nw + 16 * j], GB_LD);
            #pragma unroll
            for (int i = 0; i < 2; i++)
                #pragma unroll
                for (int j = 0; j < 4; j++)
                    wmma::mma_sync(acc[i][j], af[i], bf[j], acc[i][j]);
        }
        __syncthreads();
    }
    #pragma unroll
    for (int i = 0; i < 2; i++)
        #pragma unroll
        for (int j = 0; j < 4; j++)
            wmma::store_matrix_sync(&g_xg[(size_t)(m0 + mw + 16 * i) * G4 + n0 + nw + 16 * j],
                                    acc[i][j], G4, wmma::mem_row_major);
}

// ---------------- persistent LSTM recurrence: 2 CTAs/SM, early barrier arrive ----------------
// 256 CTAs = bt(0..7) x ut(0..31). CTA: 32 batch x 16 units (64 gate-cols), K=512.
// 128 threads = 4 warps: bh = w&1 (batch half), uo = w>>1 (unit octet 0..1).
#define BS_LD 72
#define AS_LD 520
#define DSMEM_BYTES (512*BS_LD*2 + 32*AS_LD*2)   // 107008

__global__ void __launch_bounds__(128, 2) k_lstm(const float* __restrict__ Wmlp) {
    extern __shared__ char smem[];
    __nv_bfloat16* Bs = (__nv_bfloat16*)smem;                          // [512][BS_LD]
    __nv_bfloat16* As = (__nv_bfloat16*)(smem + 512 * BS_LD * 2);      // [32][AS_LD]

    int tid = threadIdx.x, w = tid >> 5, lane = tid & 31;
    int ut = blockIdx.x & 31, bt = blockIdx.x >> 5;
    int u0 = ut * 16, b0 = bt * 32;
    int bh = (w & 1);             // batch half (16 rows)
    int uo = w >> 1;              // unit octet 0..1
    unsigned* ctr = &g_ctr[bt][0];

    // preload W_hh slice into SMEM: Bs[k][g*16+uu] = W_hh[g*512+u0+uu][k], uu in [0,16)
    for (int idx = tid; idx < 512 * 8; idx += 128) {
        int k = idx >> 3;
        int col = (idx & 7) * 8;
        int g = col >> 4, uu = col & 15;
        *(uint4*)&Bs[k * BS_LD + col] = *(const uint4*)&g_whh[(size_t)k * G4 + g * 512 + u0 + uu];
    }

    // ldmatrix addressing
    int grp = lane >> 3, rin = lane & 7;
    uint32_t As_u = (uint32_t)__cvta_generic_to_shared(As);
    uint32_t Bs_u = (uint32_t)__cvta_generic_to_shared(Bs);
    uint32_t aBase = As_u + (uint32_t)(((bh * 16 + (grp & 1) * 8 + rin) * AS_LD + (grp >> 1) * 8) * 2);
    int bRow = (grp & 1) * 8 + rin;
    int gsel = grp >> 1;          // 0/1
    uint32_t bBase01 = Bs_u + (uint32_t)((bRow * BS_LD + (gsel * 16 + uo * 8)) * 2);
    uint32_t bBase23 = Bs_u + (uint32_t)((bRow * BS_LD + ((2 + gsel) * 16 + uo * 8)) * 2);

    // cell ownership (m16n8 D fragment layout): rows {r_lo, r_lo+8}, cols {u_a, u_a+1}
    int r_lo = bh * 16 + (lane >> 2);
    int r_hi = r_lo + 8;
    int u_a  = uo * 8 + (lane & 3) * 2;
    float2 wm = __ldg((const float2*)&Wmlp[u0 + u_a]);

    float c_reg[4] = {0.f, 0.f, 0.f, 0.f};

    // xg prefetch for t=0: per gate, float2 at (row, col u0+g*512+u_a), both rows
    float2 xlo[4], xhi[4];
    {
        const float* plo = g_xg + ((size_t)0 * Bb + b0 + r_lo) * G4 + u0 + u_a;
        const float* phi = g_xg + ((size_t)0 * Bb + b0 + r_hi) * G4 + u0 + u_a;
        #pragma unroll
        for (int g = 0; g < 4; g++) {
            xlo[g] = __ldg((const float2*)(plo + g * 512));
            xhi[g] = __ldg((const float2*)(phi + g * 512));
        }
    }

    __syncthreads();

    for (int t = 0; t < Tt; t++) {
        int cur = t & 1, nxt = cur ^ 1;

        // load h (32 x 512 bf16) from L2 into As
        const __nv_bfloat16* hsrc = g_h[cur] + (size_t)b0 * Hh;
        #pragma unroll
        for (int it = 0; it < 16; it++) {
            int idx = tid + it * 128;
            int r = idx >> 6, c = (idx & 63) * 8;
            *(uint4*)&As[r * AS_LD + c] = __ldcg((const uint4*)&hsrc[(size_t)r * Hh + c]);
        }
        __syncthreads();

        // MMA: acc[gate][k-parity][4elem] -> 8 independent chains of 16
        float acc[4][2][4];
        #pragma unroll
        for (int g = 0; g < 4; g++)
            #pragma unroll
            for (int p = 0; p < 2; p++)
                #pragma unroll
                for (int e = 0; e < 4; e++) acc[g][p][e] = 0.f;

        #pragma unroll
        for (int kc = 0; kc < 16; kc++) {
            #pragma unroll
            for (int p = 0; p < 2; p++) {
                int koff = kc * 32 + p * 16;
                uint32_t a0, a1, a2, a3, q0, q1, q2, q3, s0, s1, s2, s3;
                ldsm_x4 (a0, a1, a2, a3, aBase   + (uint32_t)(koff * 2));
                ldsm_x4t(q0, q1, q2, q3, bBase01 + (uint32_t)(koff * BS_LD * 2));
                ldsm_x4t(s0, s1, s2, s3, bBase23 + (uint32_t)(koff * BS_LD * 2));
                mma16816(acc[0][p], a0, a1, a2, a3, q0, q1);
                mma16816(acc[1][p], a0, a1, a2, a3, q2, q3);
                mma16816(acc[2][p], a0, a1, a2, a3, s0, s1);
                mma16816(acc[3][p], a0, a1, a2, a3, s2, s3);
            }
        }

        // combine k-parity chains
        float gv0[4], gv1[4], gv2[4], gv3[4];
        #pragma unroll
        for (int e = 0; e < 4; e++) {
            gv0[e] = acc[0][0][e] + acc[0][1][e];
            gv1[e] = acc[1][0][e] + acc[1][1][e];
            gv2[e] = acc[2][0][e] + acc[2][1][e];
            gv3[e] = acc[3][0][e] + acc[3][1][e];
        }

        // cell (registers only): e = {lo/ua, lo/ub, hi/ua, hi/ub}
        float xv0[4] = {xlo[0].x, xlo[0].y, xhi[0].x, xhi[0].y};
        float xv1[4] = {xlo[1].x, xlo[1].y, xhi[1].x, xhi[1].y};
        float xv2[4] = {xlo[2].x, xlo[2].y, xhi[2].x, xhi[2].y};
        float xv3[4] = {xlo[3].x, xlo[3].y, xhi[3].x, xhi[3].y};
        float hv[4];
        #pragma unroll
        for (int e = 0; e < 4; e++) {
            float ig = sigm(gv0[e] + xv0[e]);
            float fg = sigm(gv1[e] + xv1[e]);
            float gg = tanh_fast(gv2[e] + xv2[e]);
            float og = sigm(gv3[e] + xv3[e]);
            float cn = fg * c_reg[e] + ig * gg;
            c_reg[e] = cn;
            hv[e] = og * tanh_fast(cn);
        }

        // write h (bf16x2 per row)
        {
            __nv_bfloat162 lo2 = __floats2bfloat162_rn(hv[0], hv[1]);
            __nv_bfloat162 hi2 = __floats2bfloat162_rn(hv[2], hv[3]);
            __stcg((unsigned*)&g_h[nxt][(size_t)(b0 + r_lo) * Hh + u0 + u_a], *(unsigned*)&lo2);
            __stcg((unsigned*)&g_h[nxt][(size_t)(b0 + r_hi) * Hh + u0 + u_a], *(unsigned*)&hi2);
        }

        // EARLY ARRIVE: publish this CTA's h as soon as stores are ordered; the
        // plog write and xg prefetch below proceed inside the poll window.
        if (t + 1 < Tt) {
            __syncthreads();
            if (tid == 0)
                asm volatile("red.release.gpu.global.add.u32 [%0], 1;" :: "l"(ctr) : "memory");
        }

        // partial logits: reduce over the 4 threads covering this row's octet
        {
            float s_lo = hv[0] * wm.x + hv[1] * wm.y;
            float s_hi = hv[2] * wm.x + hv[3] * wm.y;
            s_lo += __shfl_xor_sync(0xffffffffu, s_lo, 1);
            s_lo += __shfl_xor_sync(0xffffffffu, s_lo, 2);
            s_hi += __shfl_xor_sync(0xffffffffu, s_hi, 1);
            s_hi += __shfl_xor_sync(0xffffffffu, s_hi, 2);
            if ((lane & 3) == 0) {
                int slot = ut * 2 + uo;
                g_plog[((size_t)slot * Tt + t) * Bb + b0 + r_lo] = s_lo;
                g_plog[((size_t)slot * Tt + t) * Bb + b0 + r_hi] = s_hi;
            }
        }

        // xg prefetch for t+1 (in flight across the barrier wait)
        if (t + 1 < Tt) {
            const float* plo = g_xg + ((size_t)(t + 1) * Bb + b0 + r_lo) * G4 + u0 + u_a;
            const float* phi = g_xg + ((size_t)(t + 1) * Bb + b0 + r_hi) * G4 + u0 + u_a;
            #pragma unroll
            for (int g = 0; g < 4; g++) {
                xlo[g] = __ldg((const float2*)(plo + g * 512));
                xhi[g] = __ldg((const float2*)(phi + g * 512));
            }
        }

        // poll: wait for all 32 CTAs of this batch group
        if (t + 1 < Tt) {
            if (tid == 0) {
                unsigned tgt = 32u * (unsigned)(t + 1);
                unsigned v;
                do {
                    asm volatile("ld.acquire.gpu.global.u32 %0, [%1];" : "=r"(v) : "l"(ctr) : "memory");
                } while (v < tgt);
            }
            __syncthreads();
        }
    }
}

// ---------------- reduce partial logits -> sigmoid -> out (B, T) ----------------
__global__ void k_out(const float* __restrict__ bmlp, float* __restrict__ out) {
    int t = blockIdx.x, b = threadIdx.x;
    float s = bmlp[0];
    #pragma unroll
    for (int j = 0; j < 64; j++)
        s += g_plog[((size_t)j * Tt + t) * Bb + b];
    out[(size_t)b * Tt + t] = 1.0f / (1.0f + __expf(-s));
}

// ---------------- launch ----------------
extern "C" void kernel_launch(void* const* d_in, const int* in_sizes, int n_in,
                              void* d_out, int out_size) {
    const float* x    = (const float*)d_in[0];
    const float* Wih  = (const float*)d_in[1];
    const float* Whh  = (const float*)d_in[2];
    const float* bih  = (const float*)d_in[3];
    const float* bhh  = (const float*)d_in[4];
    const float* Wmlp = (const float*)d_in[5];
    const float* bmlp = (const float*)d_in[6];
    float* out = (float*)d_out;

    k_init<<<512, 256>>>();
    k_convert<<<4096, 256>>>(Wih, Whh, bih, bhh);
    k_transpose<<<dim3(Tt / 32, Dd / 32, Bb), dim3(32, 8)>>>(x);

    cudaFuncSetAttribute(k_gemm1, cudaFuncAttributeMaxDynamicSharedMemorySize, G1_SMEM);
    k_gemm1<<<dim3(G4 / 128, Mm / 128), 256, G1_SMEM>>>();   // n fastest

    cudaFuncSetAttribute(k_lstm, cudaFuncAttributeMaxDynamicSharedMemorySize, DSMEM_BYTES);
    k_lstm<<<256, 128, DSMEM_BYTES>>>(Wmlp);

    k_out<<<Tt, Bb>>>(bmlp, out);
}

// round 15
// speedup vs baseline: 1.3908x; 1.0331x over previous
#include <cuda_runtime.h>
#include <cuda_bf16.h>
#include <mma.h>
#include <cstdint>

using namespace nvcuda;

#define Bb 256
#define Dd 256
#define Tt 512
#define Hh 512
#define G4 2048
#define Mm (Tt*Bb)   // 131072

// ---------------- device scratch (no runtime allocation allowed) ----------------
__device__ __nv_bfloat16 g_xb[(size_t)Mm*Dd];        // xs as bf16, [t*B+b][d]
__device__ float         g_xg[(size_t)Mm*G4];        // x_gates fp32 (includes biases)
__device__ __nv_bfloat16 g_wih[(size_t)Dd*G4];       // W_ih^T bf16 [k][n]
__device__ __nv_bfloat16 g_whh[(size_t)Hh*G4];       // W_hh^T bf16 [k][n]
__device__ float         g_biasmat[16*G4];           // 16 identical rows of (b_ih+b_hh)
__device__ __nv_bfloat16 g_h[2][(size_t)Bb*Hh];      // double-buffered hidden state
__device__ float         g_plog[64*(size_t)Tt*Bb];   // partial logits per (ut,octet)
__device__ unsigned int  g_ctr[8][32];               // per batch-group counter (128B apart)

__device__ __forceinline__ float tanh_fast(float x) {
    float y; asm("tanh.approx.f32 %0, %1;" : "=f"(y) : "f"(x)); return y;
}
// sigmoid via tanh: 1 MUFU + 2 FMA (vs 2 MUFU for expf+rcp)
__device__ __forceinline__ float sigm(float x) { return fmaf(tanh_fast(x * 0.5f), 0.5f, 0.5f); }

__device__ __forceinline__ void cp16(void* dst, const void* src) {
    unsigned d = (unsigned)__cvta_generic_to_shared(dst);
    asm volatile("cp.async.cg.shared.global [%0], [%1], 16;" :: "r"(d), "l"(src));
}

__device__ __forceinline__ void ldsm_x4(uint32_t& r0, uint32_t& r1, uint32_t& r2, uint32_t& r3, uint32_t a) {
    asm volatile("ldmatrix.sync.aligned.m8n8.x4.shared.b16 {%0,%1,%2,%3}, [%4];"
                 : "=r"(r0), "=r"(r1), "=r"(r2), "=r"(r3) : "r"(a));
}
__device__ __forceinline__ void ldsm_x4t(uint32_t& r0, uint32_t& r1, uint32_t& r2, uint32_t& r3, uint32_t a) {
    asm volatile("ldmatrix.sync.aligned.m8n8.x4.trans.shared.b16 {%0,%1,%2,%3}, [%4];"
                 : "=r"(r0), "=r"(r1), "=r"(r2), "=r"(r3) : "r"(a));
}
__device__ __forceinline__ void mma16816(float* c, uint32_t a0, uint32_t a1, uint32_t a2, uint32_t a3,
                                         uint32_t b0, uint32_t b1) {
    asm volatile("mma.sync.aligned.m16n8k16.row.col.f32.bf16.bf16.f32 "
                 "{%0,%1,%2,%3},{%4,%5,%6,%7},{%8,%9},{%0,%1,%2,%3};"
                 : "+f"(c[0]), "+f"(c[1]), "+f"(c[2]), "+f"(c[3])
                 : "r"(a0), "r"(a1), "r"(a2), "r"(a3), "r"(b0), "r"(b1));
}

// ---------------- init: zero h0 and counters ----------------
__global__ void k_init() {
    int i = blockIdx.x * blockDim.x + threadIdx.x;
    if (i < 8 * 32) ((unsigned*)g_ctr)[i] = 0u;
    if (i < Bb * Hh) g_h[0][i] = __float2bfloat16(0.0f);
}

// ---------------- weight converts (transpose to [k][n], bf16) ----------------
__global__ void k_convert(const float* __restrict__ Wih, const float* __restrict__ Whh,
                          const float* __restrict__ bih, const float* __restrict__ bhh) {
    int i = blockIdx.x * blockDim.x + threadIdx.x;
    if (i < Dd * G4) {
        int k = i / G4, n = i % G4;
        g_wih[i] = __float2bfloat16(Wih[(size_t)n * Dd + k]);
    }
    if (i < Hh * G4) {
        int k = i / G4, n = i % G4;
        g_whh[i] = __float2bfloat16(Whh[(size_t)n * Hh + k]);
    }
    if (i < 16 * G4) {
        int n = i % G4;
        g_biasmat[i] = bih[n] + bhh[n];
    }
}

// ---------------- transpose x (B,D,T) -> g_xb[(t*B+b)*D + d] bf16 ----------------
__global__ void k_transpose(const float* __restrict__ x) {
    __shared__ float tile[32][33];
    int b  = blockIdx.z;
    int d0 = blockIdx.y * 32, t0 = blockIdx.x * 32;
    int tx = threadIdx.x, ty = threadIdx.y;   // 32 x 8
    const float* src = x + ((size_t)b * Dd + d0) * Tt + t0;
    for (int r = ty; r < 32; r += 8)
        tile[r][tx] = src[(size_t)r * Tt + tx];
    __syncthreads();
    for (int r = ty; r < 32; r += 8)
        g_xb[((size_t)(t0 + r) * Bb + b) * Dd + d0 + tx] = __float2bfloat16(tile[tx][r]);
}

// ---------------- GEMM1 (proven 670us): 128x128 tile, 2-stage cp.async ----------
#define GA_LD 72
#define GB_LD 136
#define G1_SMEM (2*128*GA_LD*2 + 2*64*GB_LD*2)

__global__ void __launch_bounds__(256, 2) k_gemm1() {
    extern __shared__ char smg[];
    __nv_bfloat16 (*As)[128][GA_LD] = (__nv_bfloat16(*)[128][GA_LD])smg;
    __nv_bfloat16 (*Bs)[64][GB_LD]  = (__nv_bfloat16(*)[64][GB_LD])(smg + 2*128*GA_LD*2);

    int n0 = blockIdx.x * 128, m0 = blockIdx.y * 128;   // n fastest -> A-tile reuse in L2
    int tid = threadIdx.x;
    int w = tid >> 5;
    int mw = (w >> 1) * 32, nw = (w & 1) * 64;

    auto load_stage = [&](int c, int s) {
        int k0 = c * 64;
        #pragma unroll
        for (int p = 0; p < 4; p++) {
            int idx = tid + p * 256;
            int r = idx >> 3, cc = (idx & 7) * 8;
            cp16(&As[s][r][cc], &g_xb[(size_t)(m0 + r) * Dd + k0 + cc]);
        }
        #pragma unroll
        for (int p = 0; p < 4; p++) {
            int idx = tid + p * 256;
            int r = idx >> 4, cc = (idx & 15) * 8;
            cp16(&Bs[s][r][cc], &g_wih[(size_t)(k0 + r) * G4 + n0 + cc]);
        }
        asm volatile("cp.async.commit_group;" ::: "memory");
    };

    load_stage(0, 0);

    wmma::fragment<wmma::accumulator, 16, 16, 16, float> acc[2][4];
    #pragma unroll
    for (int i = 0; i < 2; i++)
        #pragma unroll
        for (int j = 0; j < 4; j++)
            wmma::load_matrix_sync(acc[i][j], &g_biasmat[n0 + nw + 16 * j], G4, wmma::mem_row_major);

    #pragma unroll
    for (int c = 0; c < 4; c++) {
        if (c < 3) load_stage(c + 1, (c + 1) & 1);
        if (c < 3) asm volatile("cp.async.wait_group 1;" ::: "memory");
        else       asm volatile("cp.async.wait_group 0;" ::: "memory");
        __syncthreads();
        int s = c & 1;
        #pragma unroll
        for (int kk = 0; kk < 64; kk += 16) {
            wmma::fragment<wmma::matrix_a, 16, 16, 16, __nv_bfloat16, wmma::row_major> af[2];
            wmma::fragment<wmma::matrix_b, 16, 16, 16, __nv_bfloat16, wmma::row_major> bf[4];
            #pragma unroll
            for (int i = 0; i < 2; i++)
                wmma::load_matrix_sync(af[i], &As[s][mw + 16 * i][kk], GA_LD);
            #pragma unroll
            for (int j = 0; j < 4; j++)
                wmma::load_matrix_sync(bf[j], &Bs[s][kk][nw + 16 * j], GB_LD);
            #pragma unroll
            for (int i = 0; i < 2; i++)
                #pragma unroll
                for (int j = 0; j < 4; j++)
                    wmma::mma_sync(acc[i][j], af[i], bf[j], acc[i][j]);
        }
        __syncthreads();
    }
    #pragma unroll
    for (int i = 0; i < 2; i++)
        #pragma unroll
        for (int j = 0; j < 4; j++)
            wmma::store_matrix_sync(&g_xg[(size_t)(m0 + mw + 16 * i) * G4 + n0 + nw + 16 * j],
                                    acc[i][j], G4, wmma::mem_row_major);
}

// ---------------- persistent LSTM recurrence: chunk-pipelined h-load ----------------
// 256 CTAs = bt(0..7) x ut(0..31). CTA: 32 batch x 16 units (64 gate-cols), K=512.
// 128 threads = 4 warps: bh = w&1 (batch half), uo = w>>1 (unit octet 0..1).
// h-load split into 4 cp.async chunk groups; MMA runs per-chunk so chunks 1-3 load
// under chunk 0..2's MMA. Early barrier arrive after h-store (R14).
#define BS_LD 72
#define AS_LD 520
#define DSMEM_BYTES (512*BS_LD*2 + 32*AS_LD*2)   // 107008

__global__ void __launch_bounds__(128, 2) k_lstm(const float* __restrict__ Wmlp) {
    extern __shared__ char smem[];
    __nv_bfloat16* Bs = (__nv_bfloat16*)smem;                          // [512][BS_LD]
    __nv_bfloat16* As = (__nv_bfloat16*)(smem + 512 * BS_LD * 2);      // [32][AS_LD]

    int tid = threadIdx.x, w = tid >> 5, lane = tid & 31;
    int ut = blockIdx.x & 31, bt = blockIdx.x >> 5;
    int u0 = ut * 16, b0 = bt * 32;
    int bh = (w & 1);             // batch half (16 rows)
    int uo = w >> 1;              // unit octet 0..1
    unsigned* ctr = &g_ctr[bt][0];

    // preload W_hh slice into SMEM: Bs[k][g*16+uu] = W_hh[g*512+u0+uu][k], uu in [0,16)
    for (int idx = tid; idx < 512 * 8; idx += 128) {
        int k = idx >> 3;
        int col = (idx & 7) * 8;
        int g = col >> 4, uu = col & 15;
        *(uint4*)&Bs[k * BS_LD + col] = *(const uint4*)&g_whh[(size_t)k * G4 + g * 512 + u0 + uu];
    }

    // ldmatrix addressing
    int grp = lane >> 3, rin = lane & 7;
    uint32_t As_u = (uint32_t)__cvta_generic_to_shared(As);
    uint32_t Bs_u = (uint32_t)__cvta_generic_to_shared(Bs);
    uint32_t aBase = As_u + (uint32_t)(((bh * 16 + (grp & 1) * 8 + rin) * AS_LD + (grp >> 1) * 8) * 2);
    int bRow = (grp & 1) * 8 + rin;
    int gsel = grp >> 1;          // 0/1
    uint32_t bBase01 = Bs_u + (uint32_t)((bRow * BS_LD + (gsel * 16 + uo * 8)) * 2);
    uint32_t bBase23 = Bs_u + (uint32_t)((bRow * BS_LD + ((2 + gsel) * 16 + uo * 8)) * 2);

    // cell ownership (m16n8 D fragment layout): rows {r_lo, r_lo+8}, cols {u_a, u_a+1}
    int r_lo = bh * 16 + (lane >> 2);
    int r_hi = r_lo + 8;
    int u_a  = uo * 8 + (lane & 3) * 2;
    float2 wm = __ldg((const float2*)&Wmlp[u0 + u_a]);

    float c_reg[4] = {0.f, 0.f, 0.f, 0.f};

    // xg prefetch for t=0: per gate, float2 at (row, col u0+g*512+u_a), both rows
    float2 xlo[4], xhi[4];
    {
        const float* plo = g_xg + ((size_t)0 * Bb + b0 + r_lo) * G4 + u0 + u_a;
        const float* phi = g_xg + ((size_t)0 * Bb + b0 + r_hi) * G4 + u0 + u_a;
        #pragma unroll
        for (int g = 0; g < 4; g++) {
            xlo[g] = __ldg((const float2*)(plo + g * 512));
            xhi[g] = __ldg((const float2*)(phi + g * 512));
        }
    }

    __syncthreads();

    for (int t = 0; t < Tt; t++) {
        int cur = t & 1, nxt = cur ^ 1;

        // issue h load as 4 cp.async chunk groups (columns 128*c .. 128*c+127, all 32 rows)
        const __nv_bfloat16* hsrc = g_h[cur] + (size_t)b0 * Hh;
        #pragma unroll
        for (int c = 0; c < 4; c++) {
            #pragma unroll
            for (int it = 0; it < 4; it++) {
                int idx = tid + it * 128;                 // 0..511
                int r = idx >> 4, cc = (idx & 15) * 8;    // 32 rows x 128 cols
                cp16(&As[r * AS_LD + c * 128 + cc], &hsrc[(size_t)r * Hh + c * 128 + cc]);
            }
            asm volatile("cp.async.commit_group;" ::: "memory");
        }

        // MMA per chunk: acc[gate][k-parity][4elem] -> 8 independent chains
        float acc[4][2][4];
        #pragma unroll
        for (int g = 0; g < 4; g++)
            #pragma unroll
            for (int p = 0; p < 2; p++)
                #pragma unroll
                for (int e = 0; e < 4; e++) acc[g][p][e] = 0.f;

        #pragma unroll
        for (int c = 0; c < 4; c++) {
            if (c == 0)      asm volatile("cp.async.wait_group 3;" ::: "memory");
            else if (c == 1) asm volatile("cp.async.wait_group 2;" ::: "memory");
            else if (c == 2) asm volatile("cp.async.wait_group 1;" ::: "memory");
            else             asm volatile("cp.async.wait_group 0;" ::: "memory");
            __syncthreads();
            #pragma unroll
            for (int kc = 0; kc < 4; kc++) {
                #pragma unroll
                for (int p = 0; p < 2; p++) {
                    int koff = c * 128 + kc * 32 + p * 16;
                    uint32_t a0, a1, a2, a3, q0, q1, q2, q3, s0, s1, s2, s3;
                    ldsm_x4 (a0, a1, a2, a3, aBase   + (uint32_t)(koff * 2));
                    ldsm_x4t(q0, q1, q2, q3, bBase01 + (uint32_t)(koff * BS_LD * 2));
                    ldsm_x4t(s0, s1, s2, s3, bBase23 + (uint32_t)(koff * BS_LD * 2));
                    mma16816(acc[0][p], a0, a1, a2, a3, q0, q1);
                    mma16816(acc[1][p], a0, a1, a2, a3, q2, q3);
                    mma16816(acc[2][p], a0, a1, a2, a3, s0, s1);
                    mma16816(acc[3][p], a0, a1, a2, a3, s2, s3);
                }
            }
        }

        // combine k-parity chains
        float gv0[4], gv1[4], gv2[4], gv3[4];
        #pragma unroll
        for (int e = 0; e < 4; e++) {
            gv0[e] = acc[0][0][e] + acc[0][1][e];
            gv1[e] = acc[1][0][e] + acc[1][1][e];
            gv2[e] = acc[2][0][e] + acc[2][1][e];
            gv3[e] = acc[3][0][e] + acc[3][1][e];
        }

        // cell (registers only): e = {lo/ua, lo/ub, hi/ua, hi/ub}
        float xv0[4] = {xlo[0].x, xlo[0].y, xhi[0].x, xhi[0].y};
        float xv1[4] = {xlo[1].x, xlo[1].y, xhi[1].x, xhi[1].y};
        float xv2[4] = {xlo[2].x, xlo[2].y, xhi[2].x, xhi[2].y};
        float xv3[4] = {xlo[3].x, xlo[3].y, xhi[3].x, xhi[3].y};
        float hv[4];
        #pragma unroll
        for (int e = 0; e < 4; e++) {
            float ig = sigm(gv0[e] + xv0[e]);
            float fg = sigm(gv1[e] + xv1[e]);
            float gg = tanh_fast(gv2[e] + xv2[e]);
            float og = sigm(gv3[e] + xv3[e]);
            float cn = fg * c_reg[e] + ig * gg;
            c_reg[e] = cn;
            hv[e] = og * tanh_fast(cn);
        }

        // write h (bf16x2 per row)
        {
            __nv_bfloat162 lo2 = __floats2bfloat162_rn(hv[0], hv[1]);
            __nv_bfloat162 hi2 = __floats2bfloat162_rn(hv[2], hv[3]);
            __stcg((unsigned*)&g_h[nxt][(size_t)(b0 + r_lo) * Hh + u0 + u_a], *(unsigned*)&lo2);
            __stcg((unsigned*)&g_h[nxt][(size_t)(b0 + r_hi) * Hh + u0 + u_a], *(unsigned*)&hi2);
        }

        // EARLY ARRIVE: publish this CTA's h as soon as stores are ordered; the
        // plog write and xg prefetch below proceed inside the poll window.
        if (t + 1 < Tt) {
            __syncthreads();
            if (tid == 0)
                asm volatile("red.release.gpu.global.add.u32 [%0], 1;" :: "l"(ctr) : "memory");
        }

        // partial logits: reduce over the 4 threads covering this row's octet
        {
            float s_lo = hv[0] * wm.x + hv[1] * wm.y;
            float s_hi = hv[2] * wm.x + hv[3] * wm.y;
            s_lo += __shfl_xor_sync(0xffffffffu, s_lo, 1);
            s_lo += __shfl_xor_sync(0xffffffffu, s_lo, 2);
            s_hi += __shfl_xor_sync(0xffffffffu, s_hi, 1);
            s_hi += __shfl_xor_sync(0xffffffffu, s_hi, 2);
            if ((lane & 3) == 0) {
                int slot = ut * 2 + uo;
                g_plog[((size_t)slot * Tt + t) * Bb + b0 + r_lo] = s_lo;
                g_plog[((size_t)slot * Tt + t) * Bb + b0 + r_hi] = s_hi;
            }
        }

        // xg prefetch for t+1 (in flight across the barrier wait)
        if (t + 1 < Tt) {
            const float* plo = g_xg + ((size_t)(t + 1) * Bb + b0 + r_lo) * G4 + u0 + u_a;
            const float* phi = g_xg + ((size_t)(t + 1) * Bb + b0 + r_hi) * G4 + u0 + u_a;
            #pragma unroll
            for (int g = 0; g < 4; g++) {
                xlo[g] = __ldg((const float2*)(plo + g * 512));
                xhi[g] = __ldg((const float2*)(phi + g * 512));
            }
        }

        // poll: wait for all 32 CTAs of this batch group
        if (t + 1 < Tt) {
            if (tid == 0) {
                unsigned tgt = 32u * (unsigned)(t + 1);
                unsigned v;
                do {
                    asm volatile("ld.acquire.gpu.global.u32 %0, [%1];" : "=r"(v) : "l"(ctr) : "memory");
                } while (v < tgt);
            }
            __syncthreads();
        }
    }
}

// ---------------- reduce partial logits -> sigmoid -> out (B, T) ----------------
__global__ void k_out(const float* __restrict__ bmlp, float* __restrict__ out) {
    int t = blockIdx.x, b = threadIdx.x;
    float s = bmlp[0];
    #pragma unroll
    for (int j = 0; j < 64; j++)
        s += g_plog[((size_t)j * Tt + t) * Bb + b];
    out[(size_t)b * Tt + t] = 1.0f / (1.0f + __expf(-s));
}

// ---------------- launch ----------------
extern "C" void kernel_launch(void* const* d_in, const int* in_sizes, int n_in,
                              void* d_out, int out_size) {
    const float* x    = (const float*)d_in[0];
    const float* Wih  = (const float*)d_in[1];
    const float* Whh  = (const float*)d_in[2];
    const float* bih  = (const float*)d_in[3];
    const float* bhh  = (const float*)d_in[4];
    const float* Wmlp = (const float*)d_in[5];
    const float* bmlp = (const float*)d_in[6];
    float* out = (float*)d_out;

    k_init<<<512, 256>>>();
    k_convert<<<4096, 256>>>(Wih, Whh, bih, bhh);
    k_transpose<<<dim3(Tt / 32, Dd / 32, Bb), dim3(32, 8)>>>(x);

    cudaFuncSetAttribute(k_gemm1, cudaFuncAttributeMaxDynamicSharedMemorySize, G1_SMEM);
    k_gemm1<<<dim3(G4 / 128, Mm / 128), 256, G1_SMEM>>>();   // n fastest

    cudaFuncSetAttribute(k_lstm, cudaFuncAttributeMaxDynamicSharedMemorySize, DSMEM_BYTES);
    k_lstm<<<256, 128, DSMEM_BYTES>>>(Wmlp);

    k_out<<<Tt, Bb>>>(bmlp, out);
}

// round 16
// speedup vs baseline: 1.5710x; 1.1296x over previous
#include <cuda_runtime.h>
#include <cuda_bf16.h>
#include <cstdint>

#define Bb 256
#define Dd 256
#define Tt 512
#define Hh 512
#define G4 2048
#define Mm (Tt*Bb)   // 131072

// ---------------- device scratch (no runtime allocation allowed) ----------------
__device__ __nv_bfloat16 g_xb[(size_t)Mm*Dd];        // xs as bf16, [t*B+b][d]
__device__ uint4         g_xa[(size_t)Tt*8*2*16*32]; // xs packed as A-fragments (67MB)
__device__ uint4         g_wb[32*2*16*32*2];         // W_ih packed as B-fragments (1MB)
__device__ __nv_bfloat16 g_whh[(size_t)Hh*G4];       // W_hh^T bf16 [k][n]
__device__ __nv_bfloat16 g_h[2][(size_t)Bb*Hh];      // double-buffered hidden state
__device__ float         g_plog[64*(size_t)Tt*Bb];   // partial logits per (ut,octet)
__device__ unsigned int  g_ctr[8][32];               // per batch-group counter (128B apart)

__device__ __forceinline__ float tanh_fast(float x) {
    float y; asm("tanh.approx.f32 %0, %1;" : "=f"(y) : "f"(x)); return y;
}
__device__ __forceinline__ float sigm(float x) { return fmaf(tanh_fast(x * 0.5f), 0.5f, 0.5f); }

__device__ __forceinline__ void cp16(void* dst, const void* src) {
    unsigned d = (unsigned)__cvta_generic_to_shared(dst);
    asm volatile("cp.async.cg.shared.global [%0], [%1], 16;" :: "r"(d), "l"(src));
}

__device__ __forceinline__ void ldsm_x4(uint32_t& r0, uint32_t& r1, uint32_t& r2, uint32_t& r3, uint32_t a) {
    asm volatile("ldmatrix.sync.aligned.m8n8.x4.shared.b16 {%0,%1,%2,%3}, [%4];"
                 : "=r"(r0), "=r"(r1), "=r"(r2), "=r"(r3) : "r"(a));
}
__device__ __forceinline__ void ldsm_x4t(uint32_t& r0, uint32_t& r1, uint32_t& r2, uint32_t& r3, uint32_t a) {
    asm volatile("ldmatrix.sync.aligned.m8n8.x4.trans.shared.b16 {%0,%1,%2,%3}, [%4];"
                 : "=r"(r0), "=r"(r1), "=r"(r2), "=r"(r3) : "r"(a));
}
__device__ __forceinline__ void mma16816(float* c, uint32_t a0, uint32_t a1, uint32_t a2, uint32_t a3,
                                         uint32_t b0, uint32_t b1) {
    asm volatile("mma.sync.aligned.m16n8k16.row.col.f32.bf16.bf16.f32 "
                 "{%0,%1,%2,%3},{%4,%5,%6,%7},{%8,%9},{%0,%1,%2,%3};"
                 : "+f"(c[0]), "+f"(c[1]), "+f"(c[2]), "+f"(c[3])
                 : "r"(a0), "r"(a1), "r"(a2), "r"(a3), "r"(b0), "r"(b1));
}

// ---------------- init: zero h0 and counters ----------------
__global__ void k_init() {
    int i = blockIdx.x * blockDim.x + threadIdx.x;
    if (i < 8 * 32) ((unsigned*)g_ctr)[i] = 0u;
    if (i < Bb * Hh) g_h[0][i] = __float2bfloat16(0.0f);
}

// ---------------- W_hh convert (transpose to [k][n], bf16) ----------------
__global__ void k_convert(const float* __restrict__ Whh) {
    int i = blockIdx.x * blockDim.x + threadIdx.x;
    if (i < Hh * G4) {
        int k = i / G4, n = i % G4;
        g_whh[i] = __float2bfloat16(Whh[(size_t)n * Hh + k]);
    }
}

// ---------------- transpose x (B,D,T) -> g_xb[(t*B+b)*D + d] bf16 ----------------
__global__ void k_transpose(const float* __restrict__ x) {
    __shared__ float tile[32][33];
    int b  = blockIdx.z;
    int d0 = blockIdx.y * 32, t0 = blockIdx.x * 32;
    int tx = threadIdx.x, ty = threadIdx.y;   // 32 x 8
    const float* src = x + ((size_t)b * Dd + d0) * Tt + t0;
    for (int r = ty; r < 32; r += 8)
        tile[r][tx] = src[(size_t)r * Tt + tx];
    __syncthreads();
    for (int r = ty; r < 32; r += 8)
        g_xb[((size_t)(t0 + r) * Bb + b) * Dd + d0 + tx] = __float2bfloat16(tile[tx][r]);
}

// ---------------- pack xs into A-fragment layout ----------------
// g_xa[(((t*8+bt)*2+mt)*16+kc)*32+lane] = {a0,a1,a2,a3}
// a0=(r0,k0) a1=(r0+8,k0) a2=(r0,k0+8) a3=(r0+8,k0+8); r0=bt*32+mt*16+(lane>>2); k0=kc*16+(lane&3)*2
__global__ void k_packx() {
    size_t idx = (size_t)blockIdx.x * blockDim.x + threadIdx.x;   // over Tt*8*2*16*32
    int lane = idx & 31;
    int kc = (idx >> 5) & 15;
    int mt = (idx >> 9) & 1;
    int bt = (idx >> 10) & 7;
    int t  = (int)(idx >> 13);
    int r0 = bt * 32 + mt * 16 + (lane >> 2);
    int k0 = kc * 16 + (lane & 3) * 2;
    const uint32_t* xb32 = (const uint32_t*)g_xb;
    size_t row0 = ((size_t)t * Bb + r0) * 128;        // 128 uint32 per 256-bf16 row
    size_t row1 = row0 + 8 * 128;
    uint4 v;
    v.x = xb32[row0 + (k0 >> 1)];
    v.y = xb32[row1 + (k0 >> 1)];
    v.z = xb32[row0 + ((k0 + 8) >> 1)];
    v.w = xb32[row1 + ((k0 + 8) >> 1)];
    g_xa[idx] = v;
}

// ---------------- pack W_ih into B-fragment layout ----------------
// g_wb[(((ut*2+uo)*16+kc)*32+lane)*2+half]; half0 = gates{0,1}, half1 = gates{2,3}
__global__ void k_packw(const float* __restrict__ Wih) {
    int idx = blockIdx.x * blockDim.x + threadIdx.x;   // over 65536
    int half = idx & 1;
    int lane = (idx >> 1) & 31;
    int kc = (idx >> 6) & 15;
    int uo = (idx >> 10) & 1;
    int ut = idx >> 11;
    int k0 = kc * 16 + (lane & 3) * 2;
    uint32_t r[4];
    #pragma unroll
    for (int gi = 0; gi < 2; gi++) {
        int g = half * 2 + gi;
        int n = g * 512 + ut * 16 + uo * 8 + (lane >> 2);
        const float* wr = Wih + (size_t)n * Dd;
        __nv_bfloat162 b0 = __floats2bfloat162_rn(wr[k0], wr[k0 + 1]);
        __nv_bfloat162 b1 = __floats2bfloat162_rn(wr[k0 + 8], wr[k0 + 9]);
        r[gi * 2]     = *(uint32_t*)&b0;
        r[gi * 2 + 1] = *(uint32_t*)&b1;
    }
    g_wb[idx] = make_uint4(r[0], r[1], r[2], r[3]);
}

// ---------------- persistent LSTM recurrence with fused x-projection ----------------
#define BS_LD 72
#define AS_LD 520
#define DSMEM_BYTES (512*BS_LD*2 + 32*AS_LD*2)   // 107008

__global__ void __launch_bounds__(128, 2) k_lstm(const float* __restrict__ Wmlp,
                                                 const float* __restrict__ bih,
                                                 const float* __restrict__ bhh) {
    extern __shared__ char smem[];
    __nv_bfloat16* Bs = (__nv_bfloat16*)smem;                          // [512][BS_LD]
    __nv_bfloat16* As = (__nv_bfloat16*)(smem + 512 * BS_LD * 2);      // [32][AS_LD]

    int tid = threadIdx.x, w = tid >> 5, lane = tid & 31;
    int ut = blockIdx.x & 31, bt = blockIdx.x >> 5;
    int u0 = ut * 16, b0 = bt * 32;
    int bh = (w & 1);
    int uo = w >> 1;
    unsigned* ctr = &g_ctr[bt][0];

    for (int idx = tid; idx < 512 * 8; idx += 128) {
        int k = idx >> 3;
        int col = (idx & 7) * 8;
        int g = col >> 4, uu = col & 15;
        *(uint4*)&Bs[k * BS_LD + col] = *(const uint4*)&g_whh[(size_t)k * G4 + g * 512 + u0 + uu];
    }

    int grp = lane >> 3, rin = lane & 7;
    uint32_t As_u = (uint32_t)__cvta_generic_to_shared(As);
    uint32_t Bs_u = (uint32_t)__cvta_generic_to_shared(Bs);
    uint32_t aBase = As_u + (uint32_t)(((bh * 16 + (grp & 1) * 8 + rin) * AS_LD + (grp >> 1) * 8) * 2);
    int bRow = (grp & 1) * 8 + rin;
    int gsel = grp >> 1;
    uint32_t bBase01 = Bs_u + (uint32_t)((bRow * BS_LD + (gsel * 16 + uo * 8)) * 2);
    uint32_t bBase23 = Bs_u + (uint32_t)((bRow * BS_LD + ((2 + gsel) * 16 + uo * 8)) * 2);

    int r_lo = bh * 16 + (lane >> 2);
    int r_hi = r_lo + 8;
    int u_a  = uo * 8 + (lane & 3) * 2;
    float2 wm = __ldg((const float2*)&Wmlp[u0 + u_a]);

    float bias[4][2];
    #pragma unroll
    for (int g = 0; g < 4; g++) {
        int n = g * 512 + u0 + u_a;
        bias[g][0] = __ldg(&bih[n])     + __ldg(&bhh[n]);
        bias[g][1] = __ldg(&bih[n + 1]) + __ldg(&bhh[n + 1]);
    }

    float c_reg[4] = {0.f, 0.f, 0.f, 0.f};

    const uint4* wbp = g_wb + (((size_t)(ut * 2 + uo) * 16) * 32 + lane) * 2;   // +64/kc
    float xc[4][4];

    // x-projection for t=0
    {
        float xn[4][4];
        #pragma unroll
        for (int g = 0; g < 4; g++)
            #pragma unroll
            for (int e = 0; e < 4; e++) xn[g][e] = bias[g][e & 1];
        const uint4* xap = g_xa + ((((size_t)0 * 8 + bt) * 2 + bh) * 16) * 32 + lane;
        #pragma unroll
        for (int kc = 0; kc < 16; kc++) {
            uint4 av  = __ldg(&xap[kc * 32]);
            uint4 bv0 = __ldg(&wbp[kc * 64]);
            uint4 bv1 = __ldg(&wbp[kc * 64 + 1]);
            mma16816(xn[0], av.x, av.y, av.z, av.w, bv0.x, bv0.y);
            mma16816(xn[1], av.x, av.y, av.z, av.w, bv0.z, bv0.w);
            mma16816(xn[2], av.x, av.y, av.z, av.w, bv1.x, bv1.y);
            mma16816(xn[3], av.x, av.y, av.z, av.w, bv1.z, bv1.w);
        }
        #pragma unroll
        for (int g = 0; g < 4; g++)
            #pragma unroll
            for (int e = 0; e < 4; e++) xc[g][e] = xn[g][e];
    }

    __syncthreads();

    for (int t = 0; t < Tt; t++) {
        int cur = t & 1, nxt = cur ^ 1;

        const __nv_bfloat16* hsrc = g_h[cur] + (size_t)b0 * Hh;
        #pragma unroll
        for (int c = 0; c < 4; c++) {
            #pragma unroll
            for (int it = 0; it < 4; it++) {
                int idx = tid + it * 128;
                int r = idx >> 4, cc = (idx & 15) * 8;
                cp16(&As[r * AS_LD + c * 128 + cc], &hsrc[(size_t)r * Hh + c * 128 + cc]);
            }
            asm volatile("cp.async.commit_group;" ::: "memory");
        }

        float acc[4][2][4];
        #pragma unroll
        for (int g = 0; g < 4; g++)
            #pragma unroll
            for (int p = 0; p < 2; p++)
                #pragma unroll
                for (int e = 0; e < 4; e++) acc[g][p][e] = 0.f;

        #pragma unroll
        for (int c = 0; c < 4; c++) {
            if (c == 0)      asm volatile("cp.async.wait_group 3;" ::: "memory");
            else if (c == 1) asm volatile("cp.async.wait_group 2;" ::: "memory");
            else if (c == 2) asm volatile("cp.async.wait_group 1;" ::: "memory");
            else             asm volatile("cp.async.wait_group 0;" ::: "memory");
            __syncthreads();
            #pragma unroll
            for (int kc = 0; kc < 4; kc++) {
                #pragma unroll
                for (int p = 0; p < 2; p++) {
                    int koff = c * 128 + kc * 32 + p * 16;
                    uint32_t a0, a1, a2, a3, q0, q1, q2, q3, s0, s1, s2, s3;
                    ldsm_x4 (a0, a1, a2, a3, aBase   + (uint32_t)(koff * 2));
                    ldsm_x4t(q0, q1, q2, q3, bBase01 + (uint32_t)(koff * BS_LD * 2));
                    ldsm_x4t(s0, s1, s2, s3, bBase23 + (uint32_t)(koff * BS_LD * 2));
                    mma16816(acc[0][p], a0, a1, a2, a3, q0, q1);
                    mma16816(acc[1][p], a0, a1, a2, a3, q2, q3);
                    mma16816(acc[2][p], a0, a1, a2, a3, s0, s1);
                    mma16816(acc[3][p], a0, a1, a2, a3, s2, s3);
                }
            }
        }

        // cell: gates = recurrence + xc (xg + bias), registers only
        float hv[4];
        #pragma unroll
        for (int e = 0; e < 4; e++) {
            float ig = sigm(acc[0][0][e] + acc[0][1][e] + xc[0][e]);
            float fg = sigm(acc[1][0][e] + acc[1][1][e] + xc[1][e]);
            float gg = tanh_fast(acc[2][0][e] + acc[2][1][e] + xc[2][e]);
            float og = sigm(acc[3][0][e] + acc[3][1][e] + xc[3][e]);
            float cn = fg * c_reg[e] + ig * gg;
            c_reg[e] = cn;
            hv[e] = og * tanh_fast(cn);
        }

        {
            __nv_bfloat162 lo2 = __floats2bfloat162_rn(hv[0], hv[1]);
            __nv_bfloat162 hi2 = __floats2bfloat162_rn(hv[2], hv[3]);
            __stcg((unsigned*)&g_h[nxt][(size_t)(b0 + r_lo) * Hh + u0 + u_a], *(unsigned*)&lo2);
            __stcg((unsigned*)&g_h[nxt][(size_t)(b0 + r_hi) * Hh + u0 + u_a], *(unsigned*)&hi2);
        }

        // EARLY ARRIVE; plog + x-projection run inside the poll window
        if (t + 1 < Tt) {
            __syncthreads();
            if (tid == 0)
                asm volatile("red.release.gpu.global.add.u32 [%0], 1;" :: "l"(ctr) : "memory");
        }

        {
            float s_lo = hv[0] * wm.x + hv[1] * wm.y;
            float s_hi = hv[2] * wm.x + hv[3] * wm.y;
            s_lo += __shfl_xor_sync(0xffffffffu, s_lo, 1);
            s_lo += __shfl_xor_sync(0xffffffffu, s_lo, 2);
            s_hi += __shfl_xor_sync(0xffffffffu, s_hi, 1);
            s_hi += __shfl_xor_sync(0xffffffffu, s_hi, 2);
            if ((lane & 3) == 0) {
                int slot = ut * 2 + uo;
                g_plog[((size_t)slot * Tt + t) * Bb + b0 + r_lo] = s_lo;
                g_plog[((size_t)slot * Tt + t) * Bb + b0 + r_hi] = s_hi;
            }
        }

        // x-projection for t+1 (K=256, packed global frag streams)
        if (t + 1 < Tt) {
            float xn[4][4];
            #pragma unroll
            for (int g = 0; g < 4; g++)
                #pragma unroll
                for (int e = 0; e < 4; e++) xn[g][e] = bias[g][e & 1];
            const uint4* xap = g_xa + ((((size_t)(t + 1) * 8 + bt) * 2 + bh) * 16) * 32 + lane;
            #pragma unroll
            for (int kc = 0; kc < 16; kc++) {
                uint4 av  = __ldg(&xap[kc * 32]);
                uint4 bv0 = __ldg(&wbp[kc * 64]);
                uint4 bv1 = __ldg(&wbp[kc * 64 + 1]);
                mma16816(xn[0], av.x, av.y, av.z, av.w, bv0.x, bv0.y);
                mma16816(xn[1], av.x, av.y, av.z, av.w, bv0.z, bv0.w);
                mma16816(xn[2], av.x, av.y, av.z, av.w, bv1.x, bv1.y);
                mma16816(xn[3], av.x, av.y, av.z, av.w, bv1.z, bv1.w);
            }
            #pragma unroll
            for (int g = 0; g < 4; g++)
                #pragma unroll
                for (int e = 0; e < 4; e++) xc[g][e] = xn[g][e];
        }

        if (t + 1 < Tt) {
            if (tid == 0) {
                unsigned tgt = 32u * (unsigned)(t + 1);
                unsigned v;
                do {
                    asm volatile("ld.acquire.gpu.global.u32 %0, [%1];" : "=r"(v) : "l"(ctr) : "memory");
                } while (v < tgt);
            }
            __syncthreads();
        }
    }
}

// ---------------- reduce partial logits -> sigmoid -> out (B, T) ----------------
__global__ void k_out(const float* __restrict__ bmlp, float* __restrict__ out) {
    int t = blockIdx.x, b = threadIdx.x;
    float s = bmlp[0];
    #pragma unroll
    for (int j = 0; j < 64; j++)
        s += g_plog[((size_t)j * Tt + t) * Bb + b];
    out[(size_t)b * Tt + t] = 1.0f / (1.0f + __expf(-s));
}

// ---------------- launch ----------------
extern "C" void kernel_launch(void* const* d_in, const int* in_sizes, int n_in,
                              void* d_out, int out_size) {
    const float* x    = (const float*)d_in[0];
    const float* Wih  = (const float*)d_in[1];
    const float* Whh  = (const float*)d_in[2];
    const float* bih  = (const float*)d_in[3];
    const float* bhh  = (const float*)d_in[4];
    const float* Wmlp = (const float*)d_in[5];
    const float* bmlp = (const float*)d_in[6];
    float* out = (float*)d_out;

    k_init<<<512, 256>>>();
    k_convert<<<4096, 256>>>(Whh);
    k_transpose<<<dim3(Tt / 32, Dd / 32, Bb), dim3(32, 8)>>>(x);
    k_packx<<<(int)(((size_t)Tt * 8 * 2 * 16 * 32) / 256), 256>>>();
    k_packw<<<256, 256>>>(Wih);

    cudaFuncSetAttribute(k_lstm, cudaFuncAttributeMaxDynamicSharedMemorySize, DSMEM_BYTES);
    k_lstm<<<256, 128, DSMEM_BYTES>>>(Wmlp, bih, bhh);

    k_out<<<Tt, Bb>>>(bmlp, out);
}